// round 2
// baseline (speedup 1.0000x reference)
#include <cuda_runtime.h>
#include <math.h>
#include <stdint.h>

// Problem constants
#define BATCH 128
#define SEQ   128
#define DIM   100
#define QNB   4
#define SNB   4
#define KCN   4
#define RKN   10
#define TSTEPS 127          // SEQ-1 scan steps
#define NEGV  -1000000000.0f

// ---------------- device scratch (static globals; no allocations) ----------------
__device__ float g_Qemb[BATCH*SEQ*DIM];          // Eq[question[b,s]]
__device__ float g_G[BATCH*SEQ*SEQ];             // Gram: <Qemb[b,i], Qemb[b,j]>
__device__ int   g_topidx[TSTEPS*BATCH*RKN];     // top-10 history indices per (t,b), t>10
__device__ float g_qc[(size_t)TSTEPS*BATCH*5*DIM]; // qc rows per (t,b)
__device__ float g_qtw[TSTEPS*BATCH*5];          // <tanh(lin(qc,W_key,b_key)), Wq_part>
__device__ float g_H1[BATCH*DIM];
__device__ float g_H2[BATCH*DIM];
__device__ float g_HIST[BATCH*SEQ*DIM];
__device__ int   g_cm_mode;                      // 0=bool bytes, 1=int32, 2=float32

// ---------------- helpers ----------------
template<int N4>
__device__ __forceinline__ float dotw(const float* __restrict__ w, const float* x){
    const float4* w4 = reinterpret_cast<const float4*>(w);
    float acc = 0.f;
#pragma unroll
    for (int i = 0; i < N4; i++){
        float4 wv = __ldg(w4 + i);
        acc = fmaf(wv.x, x[4*i+0], acc);
        acc = fmaf(wv.y, x[4*i+1], acc);
        acc = fmaf(wv.z, x[4*i+2], acc);
        acc = fmaf(wv.w, x[4*i+3], acc);
    }
    return acc;
}

__device__ __forceinline__ float wredsum(float v){
#pragma unroll
    for (int o = 16; o; o >>= 1) v += __shfl_xor_sync(0xFFFFFFFFu, v, o);
    return v;
}

__device__ __forceinline__ float sigm(float x){ return 1.f / (1.f + expf(-x)); }

// ---------------- one-time kernels ----------------
__global__ void k_init(const float* __restrict__ h1i, const float* __restrict__ h2i,
                       float* __restrict__ out){
    int n = BATCH*SEQ*DIM;
    for (int i = blockIdx.x*blockDim.x + threadIdx.x; i < n; i += gridDim.x*blockDim.x){
        g_HIST[i] = 0.f;
        if (i < BATCH*DIM){ g_H1[i] = h1i[i]; g_H2[i] = h2i[i]; }
        if (i < BATCH*SEQ) out[i] = 0.f;
    }
}

__global__ void k_qemb(const float* __restrict__ Eq, const int* __restrict__ question){
    int n = BATCH*SEQ*DIM;
    for (int i = blockIdx.x*blockDim.x + threadIdx.x; i < n; i += gridDim.x*blockDim.x){
        int bs = i / DIM, d = i - bs*DIM;
        g_Qemb[i] = __ldg(&Eq[(size_t)question[bs]*DIM + d]);
    }
}

// Probe concept_mask dtype. Row q's column 0 is always True in the dataset, and
// with KC=4 the byte patterns of int32{0,1}, float32{0.f,1.f} and packed bools are
// mutually distinguishable over ~1000 4-byte groups.
__global__ void k_detect(const unsigned char* __restrict__ cm){
    if (blockIdx.x == 0 && threadIdx.x == 0){
        int intOK = 1, fltOK = 1;
        for (int g = 0; g < 1000; g++){
            uint32_t v = 0;
            v |= (uint32_t)cm[4*g+0];
            v |= (uint32_t)cm[4*g+1] << 8;
            v |= (uint32_t)cm[4*g+2] << 16;
            v |= (uint32_t)cm[4*g+3] << 24;
            if (!(v == 0u || v == 1u)) intOK = 0;
            if (!(v == 0u || v == 0x3F800000u)) fltOK = 0;
        }
        g_cm_mode = intOK ? 1 : (fltOK ? 2 : 0);
    }
}

__global__ void k_gmat(){
    int b = blockIdx.x;
    const float* Qb = g_Qemb + (size_t)b*SEQ*DIM;
    for (int p = threadIdx.x; p < SEQ*SEQ; p += blockDim.x){
        int i = p >> 7, j = p & 127;
        g_G[((size_t)b*SEQ + i)*SEQ + j] = dotw<25>(Qb + i*DIM, Qb + j*DIM);
    }
}

// top-10 of G[b, s, t+1] over s<t, for t in [11,126]; jax tie-break (lower index wins)
__global__ void k_topk(){
    int wg   = blockIdx.x*(blockDim.x >> 5) + (threadIdx.x >> 5);
    int lane = threadIdx.x & 31;
    if (wg >= 116*BATCH) return;
    int t = 11 + wg / BATCH;
    int b = wg % BATCH;
    const float* Gb = g_G + (size_t)b*SEQ*SEQ;
    unsigned selm = 0;  // per-lane selected bits (s = lane + 32*m)
    for (int r = 0; r < RKN; r++){
        float bv = -INFINITY; int bi = SEQ;
#pragma unroll
        for (int m = 0; m < 4; m++){
            int s = lane + 32*m;
            if (s < t && !((selm >> m) & 1u)){
                float v = __ldg(&Gb[(size_t)s*SEQ + (t+1)]);
                if (v > bv || (v == bv && s < bi)){ bv = v; bi = s; }
            }
        }
#pragma unroll
        for (int o = 16; o; o >>= 1){
            float ov = __shfl_xor_sync(0xFFFFFFFFu, bv, o);
            int   oi = __shfl_xor_sync(0xFFFFFFFFu, bi, o);
            if (ov > bv || (ov == bv && oi < bi)){ bv = ov; bi = oi; }
        }
        if ((bi & 31) == lane) selm |= 1u << (bi >> 5);
        if (lane == 0) g_topidx[((size_t)t*BATCH + b)*RKN + r] = bi;
    }
}

// qc[t,b,q,:] and qtw[t,b,q] = <tanh(lin(qc, W_key, b_key)), Wq_part>
__global__ void k_qc(const float* __restrict__ Ec, const int* __restrict__ question,
                     const int* __restrict__ concept_idx, const void* __restrict__ cmask,
                     const float* __restrict__ W_key, const float* __restrict__ b_key,
                     const float* __restrict__ W_W){
    int t = blockIdx.x / BATCH, b = blockIdx.x % BATCH;
    int tid = threadIdx.x;
    __shared__ float sqc[5*DIM];
    __shared__ float sQt[5*DIM];
    int qn = question[b*SEQ + t + 1];
    int mode = g_cm_mode;
    for (int i = tid; i < 5*DIM; i += blockDim.x){
        int q = i / DIM, d = i - q*DIM;
        float v;
        if (q == 0){
            v = g_Qemb[((size_t)b*SEQ + t + 1)*DIM + d];
        } else {
            int fi = qn*KCN + (q - 1);
            bool mk;
            if (mode == 1)      mk = ((const int*)cmask)[fi] != 0;
            else if (mode == 2) mk = ((const float*)cmask)[fi] != 0.f;
            else                mk = ((const unsigned char*)cmask)[fi] != 0;
            int ci = __ldg(&concept_idx[fi]);
            v = mk ? __ldg(&Ec[(size_t)ci*DIM + d]) : 0.f;
        }
        sqc[i] = v;
        g_qc[((size_t)(t*BATCH + b))*(5*DIM) + i] = v;
    }
    __syncthreads();
    for (int i = tid; i < 5*DIM; i += blockDim.x){
        int q = i / DIM, o = i - q*DIM;
        sQt[i] = tanhf(dotw<25>(W_key + o*DIM, sqc + q*DIM) + __ldg(&b_key[o]));
    }
    __syncthreads();
    int w = tid >> 5, lane = tid & 31;
    for (int q = w; q < 5; q += (blockDim.x >> 5)){
        float part = 0.f;
        for (int d = lane; d < DIM; d += 32) part += sQt[q*DIM + d] * __ldg(&W_W[d]);
        part = wredsum(part);
        if (lane == 0) g_qtw[((size_t)t*BATCH + b)*5 + q] = part;
    }
}

// ---------------- per-timestep kernel: one block per batch row ----------------
__global__ void __launch_bounds__(256) k_step(int t,
    const float* __restrict__ Eq, const float* __restrict__ Ec, const float* __restrict__ Er,
    const float* __restrict__ Wih1, const float* __restrict__ Whh1,
    const float* __restrict__ bih1, const float* __restrict__ bhh1,
    const float* __restrict__ Wih2, const float* __restrict__ Whh2,
    const float* __restrict__ bih2, const float* __restrict__ bhh2,
    const float* __restrict__ Wagg, const float* __restrict__ bagg,
    const float* __restrict__ Wlast, const float* __restrict__ blast,
    const float* __restrict__ Wquery, const float* __restrict__ bquery,
    const float* __restrict__ WW, const float* __restrict__ bW,
    const int* __restrict__ question, const int* __restrict__ response,
    const int* __restrict__ mask, const int* __restrict__ qnb, const int* __restrict__ snb,
    float* __restrict__ out)
{
    int b = blockIdx.x, tid = threadIdx.x;

    __shared__ float sE2[16*DIM], sU[16*DIM], sV[16*DIM];
    __shared__ float sE1[4*DIM], sV1[4*DIM], sT4[4*DIM], sW1[4*DIM];
    __shared__ float vA[DIM], vB[DIM], vC[DIM];
    __shared__ float sX[2*DIM], sGi[3*DIM], sGh[3*DIM];
    __shared__ float sH1[DIM], sH1n[DIM], sH2[DIM], sG2[DIM];
    __shared__ float sSt[11*DIM], sKt[11*DIM];
    __shared__ float sOg[55], sKtw[11], sQtw[5], sP[5];
    __shared__ int   sN1[4], sN2[16], sN3[64];

    int q_t = question[b*SEQ + t];
    int r_t = response[b*SEQ + t];
    int m_t = mask[b*SEQ + t];

    for (int d = tid; d < DIM; d += 256){ sH1[d] = g_H1[b*DIM + d]; sH2[d] = g_H2[b*DIM + d]; }

    if (m_t != 0){
        // ---- aggregate(q_t): 3-hop graph propagation ----
        if (tid < QNB) sN1[tid] = __ldg(&qnb[q_t*QNB + tid]);
        __syncthreads();
        if (tid < 16) sN2[tid] = __ldg(&snb[sN1[tid >> 2]*SNB + (tid & 3)]);
        __syncthreads();
        if (tid < 64) sN3[tid] = __ldg(&qnb[sN2[tid >> 2]*QNB + (tid & 3)]);
        for (int i = tid; i < 4*DIM; i += 256){
            int r = i / DIM, d = i - r*DIM;
            sE1[i] = __ldg(&Ec[(size_t)sN1[r]*DIM + d]);
        }
        __syncthreads();
        for (int i = tid; i < 16*DIM; i += 256){
            int k = i / DIM, d = i - k*DIM;
            float e2v = __ldg(&Eq[(size_t)sN2[k]*DIM + d]);
            float s3 = __ldg(&Ec[(size_t)sN3[4*k+0]*DIM + d]) + __ldg(&Ec[(size_t)sN3[4*k+1]*DIM + d])
                     + __ldg(&Ec[(size_t)sN3[4*k+2]*DIM + d]) + __ldg(&Ec[(size_t)sN3[4*k+3]*DIM + d]);
            sE2[i] = e2v;
            sU[i]  = e2v + 0.25f*s3;
        }
        __syncthreads();
        // stage i=0
        for (int i = tid; i < 16*DIM; i += 256){
            int k = i / DIM, o = i - k*DIM;
            sV[i] = tanhf(dotw<25>(Wagg + 2*DIM*DIM + o*DIM, sU + k*DIM) + __ldg(&bagg[2*DIM + o]));
        }
        for (int i = tid; i < 4*DIM; i += 256){
            int r = i / DIM, d = i - r*DIM;
            sT4[i] = sE1[i] + 0.25f*(sE2[(4*r+0)*DIM+d] + sE2[(4*r+1)*DIM+d]
                                   + sE2[(4*r+2)*DIM+d] + sE2[(4*r+3)*DIM+d]);
        }
        for (int d = tid; d < DIM; d += 256)
            vA[d] = __ldg(&Eq[(size_t)q_t*DIM + d]) + 0.25f*(sE1[d] + sE1[DIM+d] + sE1[2*DIM+d] + sE1[3*DIM+d]);
        __syncthreads();
        for (int i = tid; i < 4*DIM; i += 256){
            int r = i / DIM, o = i - r*DIM;
            sV1[i] = tanhf(dotw<25>(Wagg + DIM*DIM + o*DIM, sT4 + r*DIM) + __ldg(&bagg[DIM + o]));
        }
        for (int o = tid; o < DIM; o += 256)
            vB[o] = tanhf(dotw<25>(Wagg + o*DIM, vA) + __ldg(&bagg[o]));
        __syncthreads();
        // stage i=1
        for (int i = tid; i < 4*DIM; i += 256){
            int r = i / DIM, d = i - r*DIM;
            sT4[i] = sV1[i] + 0.25f*(sV[(4*r+0)*DIM+d] + sV[(4*r+1)*DIM+d]
                                   + sV[(4*r+2)*DIM+d] + sV[(4*r+3)*DIM+d]);
        }
        for (int d = tid; d < DIM; d += 256)
            vA[d] = vB[d] + 0.25f*(sV1[d] + sV1[DIM+d] + sV1[2*DIM+d] + sV1[3*DIM+d]);
        __syncthreads();
        for (int i = tid; i < 4*DIM; i += 256){
            int r = i / DIM, o = i - r*DIM;
            sW1[i] = tanhf(dotw<25>(Wagg + DIM*DIM + o*DIM, sT4 + r*DIM) + __ldg(&bagg[DIM + o]));
        }
        for (int o = tid; o < DIM; o += 256)
            vC[o] = tanhf(dotw<25>(Wagg + o*DIM, vA) + __ldg(&bagg[o]));
        __syncthreads();
        // stage i=2
        for (int d = tid; d < DIM; d += 256)
            vA[d] = vC[d] + 0.25f*(sW1[d] + sW1[DIM+d] + sW1[2*DIM+d] + sW1[3*DIM+d]);
        __syncthreads();
        for (int o = tid; o < DIM; o += 256)
            vB[o] = tanhf(dotw<25>(Wagg + o*DIM, vA) + __ldg(&bagg[o]));
        __syncthreads();
        for (int o = tid; o < DIM; o += 256)
            sX[o] = tanhf(dotw<25>(Wlast + o*DIM, vB) + __ldg(&blast[o]));
    } else {
        for (int d = tid; d < DIM; d += 256) sX[d] = g_Qemb[((size_t)b*SEQ + t)*DIM + d];
    }
    for (int d = tid; d < DIM; d += 256) sX[DIM + d] = __ldg(&Er[r_t*DIM + d]);
    __syncthreads();

    // ---- GRU1 ----
    for (int i = tid; i < 600; i += 256){
        if (i < 300) sGi[i] = dotw<50>(Wih1 + i*2*DIM, sX) + __ldg(&bih1[i]);
        else { int o = i - 300; sGh[o] = dotw<25>(Whh1 + o*DIM, sH1) + __ldg(&bhh1[o]); }
    }
    __syncthreads();
    for (int d = tid; d < DIM; d += 256){
        float r = sigm(sGi[d] + sGh[d]);
        float z = sigm(sGi[DIM + d] + sGh[DIM + d]);
        float n = tanhf(sGi[2*DIM + d] + r*sGh[2*DIM + d]);
        sH1n[d] = (1.f - z)*n + z*sH1[d];
    }
    __syncthreads();
    // ---- GRU2 -> g2 ----
    for (int i = tid; i < 600; i += 256){
        if (i < 300) sGi[i] = dotw<25>(Wih2 + i*DIM, sH1n) + __ldg(&bih2[i]);
        else { int o = i - 300; sGh[o] = dotw<25>(Whh2 + o*DIM, sH2) + __ldg(&bhh2[o]); }
    }
    __syncthreads();
    for (int d = tid; d < DIM; d += 256){
        float r = sigm(sGi[d] + sGh[d]);
        float z = sigm(sGi[DIM + d] + sGh[DIM + d]);
        float n = tanhf(sGi[2*DIM + d] + r*sGh[2*DIM + d]);
        sG2[d] = (1.f - z)*n + z*sH2[d];
    }
    __syncthreads();

    // ---- predict ----
    for (int i = tid; i < 11*DIM; i += 256){
        int s = i / DIM, d = i - s*DIM;
        float v;
        if (s == 0) v = sG2[d];
        else {
            int src = (t > RKN) ? g_topidx[((size_t)t*BATCH + b)*RKN + (s - 1)] : (s - 1);
            v = g_HIST[((size_t)b*SEQ + src)*DIM + d];
        }
        sSt[i] = v;
    }
    if (tid < 5) sQtw[tid] = g_qtw[((size_t)t*BATCH + b)*5 + tid];
    __syncthreads();
    for (int i = tid; i < 11*DIM; i += 256){
        int s = i / DIM, o = i - s*DIM;
        sKt[i] = tanhf(dotw<25>(Wquery + o*DIM, sSt + s*DIM) + __ldg(&bquery[o]));
    }
    __syncthreads();
    int w = tid >> 5, lane = tid & 31;
    for (int s = w; s < 11; s += 8){
        float part = 0.f;
        for (int d = lane; d < DIM; d += 32) part += sKt[s*DIM + d] * __ldg(&WW[DIM + d]);
        part = wredsum(part);
        if (lane == 0) sKtw[s] = part;
    }
    const float* qcb = g_qc + ((size_t)(t*BATCH + b))*(5*DIM);
    for (int task = w; task < 55; task += 8){
        int q = task / 11, s = task - q*11;
        float part = 0.f;
        for (int d = lane; d < DIM; d += 32) part += __ldg(&qcb[q*DIM + d]) * sSt[s*DIM + d];
        part = wredsum(part);
        if (lane == 0) sOg[task] = part;
    }
    __syncthreads();
    if (tid < 5){
        int q = tid;
        float bw0 = __ldg(&bW[0]);
        float tmp[11]; float mx = -INFINITY;
#pragma unroll
        for (int s = 0; s < 11; s++){
            bool valid = (s == 0) || (t > RKN) || ((s - 1) < t);
            float v = valid ? (sQtw[q] + sKtw[s] + bw0) : NEGV;
            tmp[s] = v; mx = fmaxf(mx, v);
        }
        float se = 0.f, acc = 0.f;
#pragma unroll
        for (int s = 0; s < 11; s++){
            float e = expf(tmp[s] - mx);
            se += e; acc += e * sOg[q*11 + s];
        }
        sP[q] = acc / se;
    }
    __syncthreads();
    if (tid == 0){
        float p = sP[0] + sP[1] + sP[2] + sP[3] + sP[4];
        int col = (t == 0) ? 0 : (t + 1);
        out[b*SEQ + col] = p;
    }
    // ---- state updates (after all reads; block-private batch row) ----
    for (int d = tid; d < DIM; d += 256){
        g_H1[b*DIM + d] = sH1n[d];
        if (t > 0){
            g_H2[b*DIM + d] = sG2[d];
            g_HIST[((size_t)b*SEQ + t)*DIM + d] = sG2[d];
        }
    }
}

// ---------------- launch ----------------
extern "C" void kernel_launch(void* const* d_in, const int* in_sizes, int n_in,
                              void* d_out, int out_size){
    const float* Eq     = (const float*)d_in[0];
    const float* Ec     = (const float*)d_in[1];
    const float* Er     = (const float*)d_in[2];
    const float* Wih1   = (const float*)d_in[3];
    const float* Whh1   = (const float*)d_in[4];
    const float* bih1   = (const float*)d_in[5];
    const float* bhh1   = (const float*)d_in[6];
    const float* Wih2   = (const float*)d_in[7];
    const float* Whh2   = (const float*)d_in[8];
    const float* bih2   = (const float*)d_in[9];
    const float* bhh2   = (const float*)d_in[10];
    const float* Wagg   = (const float*)d_in[11];
    const float* bagg   = (const float*)d_in[12];
    const float* Wlast  = (const float*)d_in[13];
    const float* blast  = (const float*)d_in[14];
    const float* Wquery = (const float*)d_in[15];
    const float* bquery = (const float*)d_in[16];
    const float* Wkey   = (const float*)d_in[17];
    const float* bkey   = (const float*)d_in[18];
    const float* WW     = (const float*)d_in[19];
    const float* bW     = (const float*)d_in[20];
    const float* h1i    = (const float*)d_in[21];
    const float* h2i    = (const float*)d_in[22];
    const int* question = (const int*)d_in[23];
    const int* response = (const int*)d_in[24];
    const int* maskp    = (const int*)d_in[25];
    const int* qnb      = (const int*)d_in[26];
    const int* snb      = (const int*)d_in[27];
    const int* cidx     = (const int*)d_in[28];
    const void* cmask   = d_in[29];
    float* out = (float*)d_out;

    // precompute (parallel, off the sequential critical path)
    k_init<<<1024, 256>>>(h1i, h2i, out);
    k_qemb<<<2048, 256>>>(Eq, question);
    k_detect<<<1, 32>>>((const unsigned char*)cmask);
    k_gmat<<<BATCH, 256>>>();
    {
        int nwarp = 116*BATCH;
        int nb = (nwarp + 7) / 8;
        k_topk<<<nb, 256>>>();
    }
    k_qc<<<TSTEPS*BATCH, 128>>>(Ec, question, cidx, cmask, Wkey, bkey, WW);

    // sequential scan
    for (int t = 0; t < TSTEPS; t++){
        k_step<<<BATCH, 256>>>(t,
            Eq, Ec, Er, Wih1, Whh1, bih1, bhh1, Wih2, Whh2, bih2, bhh2,
            Wagg, bagg, Wlast, blast, Wquery, bquery, WW, bW,
            question, response, maskp, qnb, snb, out);
    }
}

// round 4
// speedup vs baseline: 3.0012x; 3.0012x over previous
#include <cuda_runtime.h>
#include <math.h>
#include <stdint.h>

#define BATCH 128
#define SEQ   128
#define DIM   100
#define QNB   4
#define SNB   4
#define KCN   4
#define RKN   10
#define TSTEPS 127
#define NEGV  -1000000000.0f

// ---------------- device scratch (no allocations) ----------------
__device__ float g_Qemb[BATCH*SEQ*DIM];
__device__ float g_G[(size_t)BATCH*SEQ*SEQ];
__device__ int   g_top[TSTEPS*BATCH*RKN];
__device__ float g_qc[(size_t)TSTEPS*BATCH*5*DIM];
__device__ float g_qtw[TSTEPS*BATCH*5];
__device__ float g_EMB[(size_t)TSTEPS*BATCH*DIM];
__device__ float g_GI1[(size_t)TSTEPS*BATCH*300];
__device__ float g_gier[2*300];
__device__ float g_HIST[(size_t)BATCH*SEQ*DIM];
__device__ int   g_cm_mode;

// ---------------- helpers ----------------
__device__ __forceinline__ float sigm(float x){ return 1.f/(1.f+expf(-x)); }

__device__ __forceinline__ float wredsum(float v){
#pragma unroll
    for (int o = 16; o; o >>= 1) v += __shfl_xor_sync(0xFFFFFFFFu, v, o);
    return v;
}

template<int N4>
__device__ __forceinline__ float dotw(const float* __restrict__ w, const float* x){
    const float4* w4 = reinterpret_cast<const float4*>(w);
    float acc = 0.f;
#pragma unroll
    for (int i = 0; i < N4; i++){
        float4 wv = __ldg(w4+i);
        acc = fmaf(wv.x, x[4*i+0], acc);
        acc = fmaf(wv.y, x[4*i+1], acc);
        acc = fmaf(wv.z, x[4*i+2], acc);
        acc = fmaf(wv.w, x[4*i+3], acc);
    }
    return acc;
}

// two-vector dot against one weight row, weight in SMEM
__device__ __forceinline__ void dot2s(const float* w, const float* x0, const float* x1,
                                      float& a0, float& a1){
    const float4* w4 = (const float4*)w;
    const float4* p0 = (const float4*)x0;
    const float4* p1 = (const float4*)x1;
#pragma unroll
    for (int i = 0; i < 25; i++){
        float4 wv = w4[i];
        float4 u = p0[i], v = p1[i];
        a0 = fmaf(wv.x,u.x,a0); a0 = fmaf(wv.y,u.y,a0); a0 = fmaf(wv.z,u.z,a0); a0 = fmaf(wv.w,u.w,a0);
        a1 = fmaf(wv.x,v.x,a1); a1 = fmaf(wv.y,v.y,a1); a1 = fmaf(wv.z,v.z,a1); a1 = fmaf(wv.w,v.w,a1);
    }
}

// two-vector dot against one weight row, weight in GMEM
__device__ __forceinline__ void dot2g(const float* __restrict__ w, const float* x0, const float* x1,
                                      float& a0, float& a1){
    const float4* w4 = (const float4*)w;
    const float4* p0 = (const float4*)x0;
    const float4* p1 = (const float4*)x1;
#pragma unroll
    for (int i = 0; i < 25; i++){
        float4 wv = __ldg(w4+i);
        float4 u = p0[i], v = p1[i];
        a0 = fmaf(wv.x,u.x,a0); a0 = fmaf(wv.y,u.y,a0); a0 = fmaf(wv.z,u.z,a0); a0 = fmaf(wv.w,u.w,a0);
        a1 = fmaf(wv.x,v.x,a1); a1 = fmaf(wv.y,v.y,a1); a1 = fmaf(wv.z,v.z,a1); a1 = fmaf(wv.w,v.w,a1);
    }
}

// four-vector dot, weight in GMEM, x in SMEM
__device__ __forceinline__ void dot4(const float* __restrict__ w,
        const float* x0, const float* x1, const float* x2, const float* x3,
        float& a0, float& a1, float& a2, float& a3){
    const float4* w4 = (const float4*)w;
    const float4* p0 = (const float4*)x0;
    const float4* p1 = (const float4*)x1;
    const float4* p2 = (const float4*)x2;
    const float4* p3 = (const float4*)x3;
#pragma unroll
    for (int i = 0; i < 25; i++){
        float4 wv = __ldg(w4+i);
        float4 u0 = p0[i], u1 = p1[i], u2 = p2[i], u3 = p3[i];
        a0 = fmaf(wv.x,u0.x,a0); a0 = fmaf(wv.y,u0.y,a0); a0 = fmaf(wv.z,u0.z,a0); a0 = fmaf(wv.w,u0.w,a0);
        a1 = fmaf(wv.x,u1.x,a1); a1 = fmaf(wv.y,u1.y,a1); a1 = fmaf(wv.z,u1.z,a1); a1 = fmaf(wv.w,u1.w,a1);
        a2 = fmaf(wv.x,u2.x,a2); a2 = fmaf(wv.y,u2.y,a2); a2 = fmaf(wv.z,u2.z,a2); a2 = fmaf(wv.w,u2.w,a2);
        a3 = fmaf(wv.x,u3.x,a3); a3 = fmaf(wv.y,u3.y,a3); a3 = fmaf(wv.z,u3.z,a3); a3 = fmaf(wv.w,u3.w,a3);
    }
}

// ---------------- one-time kernels ----------------
__global__ void k_detect(const unsigned char* __restrict__ cm){
    if (blockIdx.x == 0 && threadIdx.x == 0){
        int intOK = 1, fltOK = 1;
        for (int g = 0; g < 1000; g++){
            uint32_t v = 0;
            v |= (uint32_t)cm[4*g+0];
            v |= (uint32_t)cm[4*g+1] << 8;
            v |= (uint32_t)cm[4*g+2] << 16;
            v |= (uint32_t)cm[4*g+3] << 24;
            if (!(v == 0u || v == 1u)) intOK = 0;
            if (!(v == 0u || v == 0x3F800000u)) fltOK = 0;
        }
        g_cm_mode = intOK ? 1 : (fltOK ? 2 : 0);
    }
}

__global__ void k_qemb(const float* __restrict__ Eq, const int* __restrict__ question){
    int n = BATCH*SEQ*DIM;
    for (int i = blockIdx.x*blockDim.x + threadIdx.x; i < n; i += gridDim.x*blockDim.x){
        int bs = i / DIM, d = i - bs*DIM;
        g_Qemb[i] = __ldg(&Eq[(size_t)question[bs]*DIM + d]);
    }
}

__global__ void k_init(float* __restrict__ out){
    int n = BATCH*SEQ*DIM;
    for (int i = blockIdx.x*blockDim.x + threadIdx.x; i < n; i += gridDim.x*blockDim.x){
        g_HIST[i] = 0.f;
        if (i < BATCH*SEQ) out[i] = 0.f;
    }
}

// Gram matrix, register-tiled 4x4; grid (4, 128), 256 threads
__global__ void __launch_bounds__(256) k_gmat(){
    int b = blockIdx.y;
    int i0 = blockIdx.x * 32;
    int tid = threadIdx.x;
    __shared__ __align__(16) float sQ[32*DIM];
    const float* Qb = g_Qemb + (size_t)b*SEQ*DIM;
    for (int i = tid; i < 32*DIM; i += 256){
        int r = i / DIM, d = i - r*DIM;
        sQ[i] = Qb[(size_t)(i0 + r)*DIM + d];
    }
    __syncthreads();
    int ti = (tid >> 5) * 4;
    int tj = (tid & 31) * 4;
    float acc[4][4];
#pragma unroll
    for (int a = 0; a < 4; a++)
#pragma unroll
        for (int c = 0; c < 4; c++) acc[a][c] = 0.f;
    const float4* qi0 = (const float4*)(sQ + (ti+0)*DIM);
    const float4* qi1 = (const float4*)(sQ + (ti+1)*DIM);
    const float4* qi2 = (const float4*)(sQ + (ti+2)*DIM);
    const float4* qi3 = (const float4*)(sQ + (ti+3)*DIM);
    const float4* qj0 = (const float4*)(Qb + (size_t)(tj+0)*DIM);
    const float4* qj1 = (const float4*)(Qb + (size_t)(tj+1)*DIM);
    const float4* qj2 = (const float4*)(Qb + (size_t)(tj+2)*DIM);
    const float4* qj3 = (const float4*)(Qb + (size_t)(tj+3)*DIM);
#pragma unroll
    for (int k = 0; k < 25; k++){
        float4 A0 = qi0[k], A1 = qi1[k], A2 = qi2[k], A3 = qi3[k];
        float4 B0 = __ldg(qj0+k), B1 = __ldg(qj1+k), B2 = __ldg(qj2+k), B3 = __ldg(qj3+k);
#define GM(a,c,A,B) acc[a][c]=fmaf(A.x,B.x,acc[a][c]); acc[a][c]=fmaf(A.y,B.y,acc[a][c]); acc[a][c]=fmaf(A.z,B.z,acc[a][c]); acc[a][c]=fmaf(A.w,B.w,acc[a][c]);
        GM(0,0,A0,B0) GM(0,1,A0,B1) GM(0,2,A0,B2) GM(0,3,A0,B3)
        GM(1,0,A1,B0) GM(1,1,A1,B1) GM(1,2,A1,B2) GM(1,3,A1,B3)
        GM(2,0,A2,B0) GM(2,1,A2,B1) GM(2,2,A2,B2) GM(2,3,A2,B3)
        GM(3,0,A3,B0) GM(3,1,A3,B1) GM(3,2,A3,B2) GM(3,3,A3,B3)
#undef GM
    }
    float* Gb = g_G + (size_t)b*SEQ*SEQ;
#pragma unroll
    for (int a = 0; a < 4; a++)
#pragma unroll
        for (int c = 0; c < 4; c++)
            Gb[(size_t)(i0+ti+a)*SEQ + (tj+c)] = acc[a][c];
}

// top-10 with jax tie-break (lower index wins), t in [11,126]
__global__ void k_topk(){
    int wg   = blockIdx.x*(blockDim.x >> 5) + (threadIdx.x >> 5);
    int lane = threadIdx.x & 31;
    if (wg >= 116*BATCH) return;
    int t = 11 + wg / BATCH;
    int b = wg % BATCH;
    const float* Gb = g_G + (size_t)b*SEQ*SEQ;
    unsigned selm = 0;
    for (int r = 0; r < RKN; r++){
        float bv = -INFINITY; int bi = SEQ;
#pragma unroll
        for (int m = 0; m < 4; m++){
            int s = lane + 32*m;
            if (s < t && !((selm >> m) & 1u)){
                float v = __ldg(&Gb[(size_t)s*SEQ + (t+1)]);
                if (v > bv || (v == bv && s < bi)){ bv = v; bi = s; }
            }
        }
#pragma unroll
        for (int o = 16; o; o >>= 1){
            float ov = __shfl_xor_sync(0xFFFFFFFFu, bv, o);
            int   oi = __shfl_xor_sync(0xFFFFFFFFu, bi, o);
            if (ov > bv || (ov == bv && oi < bi)){ bv = ov; bi = oi; }
        }
        if ((bi & 31) == lane) selm |= 1u << (bi >> 5);
        if (lane == 0) g_top[((size_t)t*BATCH + b)*RKN + r] = bi;
    }
}

// qc[t,b] rows and qtw[t,b][q]
__global__ void k_qc(const float* __restrict__ Ec, const int* __restrict__ question,
                     const int* __restrict__ concept_idx, const void* __restrict__ cmask,
                     const float* __restrict__ W_key, const float* __restrict__ b_key,
                     const float* __restrict__ W_W){
    int t = blockIdx.x / BATCH, b = blockIdx.x % BATCH;
    int tid = threadIdx.x;
    __shared__ __align__(16) float sqc[5*DIM];
    __shared__ __align__(16) float sQt[5*DIM];
    int qn = question[b*SEQ + t + 1];
    int mode = g_cm_mode;
    for (int i = tid; i < 5*DIM; i += blockDim.x){
        int q = i / DIM, d = i - q*DIM;
        float v;
        if (q == 0){
            v = g_Qemb[((size_t)b*SEQ + t + 1)*DIM + d];
        } else {
            int fi = qn*KCN + (q - 1);
            bool mk;
            if (mode == 1)      mk = ((const int*)cmask)[fi] != 0;
            else if (mode == 2) mk = ((const float*)cmask)[fi] != 0.f;
            else                mk = ((const unsigned char*)cmask)[fi] != 0;
            int ci = __ldg(&concept_idx[fi]);
            v = mk ? __ldg(&Ec[(size_t)ci*DIM + d]) : 0.f;
        }
        sqc[i] = v;
        g_qc[((size_t)(t*BATCH + b))*(5*DIM) + i] = v;
    }
    __syncthreads();
    for (int i = tid; i < 5*DIM; i += blockDim.x){
        int q = i / DIM, o = i - q*DIM;
        sQt[i] = tanhf(dotw<25>(W_key + o*DIM, sqc + q*DIM) + __ldg(&b_key[o]));
    }
    __syncthreads();
    int w = tid >> 5, lane = tid & 31;
    for (int q = w; q < 5; q += (blockDim.x >> 5)){
        float part = 0.f;
        for (int d = lane; d < DIM; d += 32) part += sQt[q*DIM + d] * __ldg(&W_W[d]);
        part = wredsum(part);
        if (lane == 0) g_qtw[((size_t)t*BATCH + b)*5 + q] = part;
    }
}

// aggregate(q_t) for ALL (t,b), or Eq copy when mask==0
__global__ void __launch_bounds__(128) k_aggall(
    const float* __restrict__ Eq, const float* __restrict__ Ec,
    const int* __restrict__ question, const int* __restrict__ mask,
    const int* __restrict__ qnb, const int* __restrict__ snb,
    const float* __restrict__ Wagg, const float* __restrict__ bagg,
    const float* __restrict__ Wlast, const float* __restrict__ blast)
{
    int tb = blockIdx.x;
    int t = tb >> 7, b = tb & 127;
    int tid = threadIdx.x;
    int q_t = question[b*SEQ + t];
    float* dst = g_EMB + (size_t)tb*DIM;
    if (mask[b*SEQ + t] == 0){
        for (int d = tid; d < DIM; d += 128) dst[d] = __ldg(&Eq[(size_t)q_t*DIM + d]);
        return;
    }
    __shared__ __align__(16) float sE1[4*DIM], sE2[16*DIM], sU[16*DIM], sV[16*DIM];
    __shared__ __align__(16) float sV1[4*DIM], sT4[4*DIM], sW1[4*DIM];
    __shared__ __align__(16) float vA[DIM], vB[DIM], vC[DIM];
    __shared__ int sN1[4], sN2[16], sN3[64];

    if (tid < QNB) sN1[tid] = __ldg(&qnb[q_t*QNB + tid]);
    __syncthreads();
    if (tid < 16) sN2[tid] = __ldg(&snb[sN1[tid >> 2]*SNB + (tid & 3)]);
    __syncthreads();
    if (tid < 64) sN3[tid] = __ldg(&qnb[sN2[tid >> 2]*QNB + (tid & 3)]);
    for (int i = tid; i < 4*DIM; i += 128){
        int r = i / DIM, d = i - r*DIM;
        sE1[i] = __ldg(&Ec[(size_t)sN1[r]*DIM + d]);
    }
    __syncthreads();
    for (int i = tid; i < 16*DIM; i += 128){
        int k = i / DIM, d = i - k*DIM;
        float e2v = __ldg(&Eq[(size_t)sN2[k]*DIM + d]);
        float s3 = __ldg(&Ec[(size_t)sN3[4*k+0]*DIM + d]) + __ldg(&Ec[(size_t)sN3[4*k+1]*DIM + d])
                 + __ldg(&Ec[(size_t)sN3[4*k+2]*DIM + d]) + __ldg(&Ec[(size_t)sN3[4*k+3]*DIM + d]);
        sE2[i] = e2v;
        sU[i]  = e2v + 0.25f*s3;
    }
    __syncthreads();
    // stage i=0
    for (int task = tid; task < 4*DIM; task += 128){
        int o = task >> 2, kb = (task & 3) * 4;
        float a0=0.f,a1=0.f,a2=0.f,a3=0.f;
        dot4(Wagg + 2*DIM*DIM + o*DIM, sU+(kb+0)*DIM, sU+(kb+1)*DIM, sU+(kb+2)*DIM, sU+(kb+3)*DIM, a0,a1,a2,a3);
        float bb = __ldg(&bagg[2*DIM + o]);
        sV[(kb+0)*DIM+o] = tanhf(a0+bb);
        sV[(kb+1)*DIM+o] = tanhf(a1+bb);
        sV[(kb+2)*DIM+o] = tanhf(a2+bb);
        sV[(kb+3)*DIM+o] = tanhf(a3+bb);
    }
    for (int i = tid; i < 4*DIM; i += 128){
        int r = i / DIM, d = i - r*DIM;
        sT4[i] = sE1[i] + 0.25f*(sE2[(4*r+0)*DIM+d] + sE2[(4*r+1)*DIM+d]
                               + sE2[(4*r+2)*DIM+d] + sE2[(4*r+3)*DIM+d]);
    }
    for (int d = tid; d < DIM; d += 128)
        vA[d] = __ldg(&Eq[(size_t)q_t*DIM + d]) + 0.25f*(sE1[d] + sE1[DIM+d] + sE1[2*DIM+d] + sE1[3*DIM+d]);
    __syncthreads();
    for (int o = tid; o < DIM; o += 128){
        float a0=0.f,a1=0.f,a2=0.f,a3=0.f;
        dot4(Wagg + DIM*DIM + o*DIM, sT4, sT4+DIM, sT4+2*DIM, sT4+3*DIM, a0,a1,a2,a3);
        float bb = __ldg(&bagg[DIM + o]);
        sV1[o] = tanhf(a0+bb); sV1[DIM+o] = tanhf(a1+bb);
        sV1[2*DIM+o] = tanhf(a2+bb); sV1[3*DIM+o] = tanhf(a3+bb);
        vB[o] = tanhf(dotw<25>(Wagg + o*DIM, vA) + __ldg(&bagg[o]));
    }
    __syncthreads();
    // stage i=1
    for (int i = tid; i < 4*DIM; i += 128){
        int r = i / DIM, d = i - r*DIM;
        sT4[i] = sV1[i] + 0.25f*(sV[(4*r+0)*DIM+d] + sV[(4*r+1)*DIM+d]
                               + sV[(4*r+2)*DIM+d] + sV[(4*r+3)*DIM+d]);
    }
    for (int d = tid; d < DIM; d += 128)
        vA[d] = vB[d] + 0.25f*(sV1[d] + sV1[DIM+d] + sV1[2*DIM+d] + sV1[3*DIM+d]);
    __syncthreads();
    for (int o = tid; o < DIM; o += 128){
        float a0=0.f,a1=0.f,a2=0.f,a3=0.f;
        dot4(Wagg + DIM*DIM + o*DIM, sT4, sT4+DIM, sT4+2*DIM, sT4+3*DIM, a0,a1,a2,a3);
        float bb = __ldg(&bagg[DIM + o]);
        sW1[o] = tanhf(a0+bb); sW1[DIM+o] = tanhf(a1+bb);
        sW1[2*DIM+o] = tanhf(a2+bb); sW1[3*DIM+o] = tanhf(a3+bb);
        vC[o] = tanhf(dotw<25>(Wagg + o*DIM, vA) + __ldg(&bagg[o]));
    }
    __syncthreads();
    // stage i=2
    for (int d = tid; d < DIM; d += 128)
        vA[d] = vC[d] + 0.25f*(sW1[d] + sW1[DIM+d] + sW1[2*DIM+d] + sW1[3*DIM+d]);
    __syncthreads();
    for (int o = tid; o < DIM; o += 128)
        vB[o] = tanhf(dotw<25>(Wagg + o*DIM, vA) + __ldg(&bagg[o]));
    __syncthreads();
    for (int o = tid; o < DIM; o += 128)
        dst[o] = tanhf(dotw<25>(Wlast + o*DIM, vB) + __ldg(&blast[o]));
}

// gier[r][o] = Wih1[o, D:2D] @ Er[r] + bih1[o]
__global__ void k_gier(const float* __restrict__ Wih1, const float* __restrict__ bih1,
                       const float* __restrict__ Er){
    int idx = blockIdx.x*blockDim.x + threadIdx.x;
    if (idx >= 600) return;
    int r = idx / 300, o = idx - r*300;
    g_gier[idx] = dotw<25>(Wih1 + o*2*DIM + DIM, Er + r*DIM) + __ldg(&bih1[o]);
}

// gi1[t,b,o] = Wih1[o,:D] @ emb[t,b] + gier[r_t]; grid (TSTEPS, 2)
__global__ void __launch_bounds__(256) k_gi1(const float* __restrict__ Wih1,
                                             const int* __restrict__ response){
    int t = blockIdx.x, zb = blockIdx.y;
    int tid = threadIdx.x;
    __shared__ __align__(16) float sE[DIM*64];   // [d][b]
    __shared__ int sRt[64];
    for (int i = tid; i < 64*DIM; i += 256){
        int bb = i / DIM, d = i - bb*DIM;
        sE[d*64 + bb] = g_EMB[((size_t)t*BATCH + zb*64 + bb)*DIM + d];
    }
    if (tid < 64) sRt[tid] = response[(zb*64 + tid)*SEQ + t];
    __syncthreads();
    for (int tt = tid; tt < 600; tt += 256){      // 75 rowgroups x 8 batchgroups
        int ro = (tt >> 3) * 4;
        int bo = (tt & 7) * 8;
        float acc[4][8];
#pragma unroll
        for (int i = 0; i < 4; i++)
#pragma unroll
            for (int j = 0; j < 8; j++) acc[i][j] = 0.f;
        for (int k = 0; k < DIM; k++){
            float w0 = __ldg(&Wih1[(size_t)(ro+0)*2*DIM + k]);
            float w1 = __ldg(&Wih1[(size_t)(ro+1)*2*DIM + k]);
            float w2 = __ldg(&Wih1[(size_t)(ro+2)*2*DIM + k]);
            float w3 = __ldg(&Wih1[(size_t)(ro+3)*2*DIM + k]);
            const float* e = sE + k*64 + bo;
#pragma unroll
            for (int j = 0; j < 8; j++){
                float ev = e[j];
                acc[0][j] = fmaf(w0, ev, acc[0][j]);
                acc[1][j] = fmaf(w1, ev, acc[1][j]);
                acc[2][j] = fmaf(w2, ev, acc[2][j]);
                acc[3][j] = fmaf(w3, ev, acc[3][j]);
            }
        }
#pragma unroll
        for (int i = 0; i < 4; i++)
#pragma unroll
            for (int j = 0; j < 8; j++){
                int b = zb*64 + bo + j;
                int o = ro + i;
                g_GI1[((size_t)t*BATCH + b)*300 + o] = acc[i][j] + g_gier[sRt[bo+j]*300 + o];
            }
    }
}

// ---------------- persistent scan: 64 blocks, 2 batch rows each ----------------
__global__ void __launch_bounds__(256) k_scan(
    const float* __restrict__ Whh1, const float* __restrict__ bhh1,
    const float* __restrict__ Wih2, const float* __restrict__ bih2,
    const float* __restrict__ Whh2, const float* __restrict__ bhh2,
    const float* __restrict__ Wquery, const float* __restrict__ bquery,
    const float* __restrict__ WW, const float* __restrict__ bW,
    const float* __restrict__ h1i, const float* __restrict__ h2i,
    float* __restrict__ out)
{
    extern __shared__ __align__(16) float dyn[];
    float* sWhh1 = dyn;            // 30000 floats
    float* sWq   = dyn + 30000;    // 10000 floats
    __shared__ __align__(16) float sH1[2][DIM], sH1n[2][DIM], sH2[2][DIM], sG2[2][DIM];
    __shared__ __align__(16) float sGh[2][300], sGi2[2][300], sGh2[2][300], sGi1[2][300];
    __shared__ __align__(16) float sSt[2][11*DIM], sKt0[2][DIM];
    __shared__ float sOg[2][55], sQtw[2][5], sP[2][5], sKtw0[2];
    __shared__ float sCache[2][SEQ];
    __shared__ float sb1[300], sb2i[300], sb2h[300], sbq[DIM], sWk[DIM];
    __shared__ float sKz, sBW0;
    __shared__ int sSrc[2][RKN];

    int tid = threadIdx.x;
    int b0 = blockIdx.x*2;

    for (int i = tid; i < 30000; i += 256) sWhh1[i] = Whh1[i];
    for (int i = tid; i < 10000; i += 256) sWq[i] = Wquery[i];
    for (int i = tid; i < 300; i += 256){ sb1[i]=bhh1[i]; sb2i[i]=bih2[i]; sb2h[i]=bhh2[i]; }
    for (int i = tid; i < DIM; i += 256){
        sbq[i] = bquery[i]; sWk[i] = WW[DIM+i];
        sH1[0][i] = h1i[b0*DIM+i];     sH1[1][i] = h1i[(b0+1)*DIM+i];
        sH2[0][i] = h2i[b0*DIM+i];     sH2[1][i] = h2i[(b0+1)*DIM+i];
    }
    if (tid == 0) sBW0 = bW[0];
    __syncthreads();
    if (tid < 32){
        float v = 0.f;
        for (int d = tid; d < DIM; d += 32) v += tanhf(sbq[d]) * sWk[d];
        v = wredsum(v);
        if (tid == 0) sKz = v;
    }
    __syncthreads();
    for (int i = tid; i < 2*SEQ; i += 256) sCache[i >> 7][i & 127] = sKz;
    __syncthreads();

    for (int t = 0; t < TSTEPS; t++){
        // A: gh1 = Whh1@h1 + bhh1 (smem weights), load gi1 rows
        for (int o = tid; o < 300; o += 256){
            float a0 = sb1[o], a1 = sb1[o];
            dot2s(sWhh1 + o*DIM, sH1[0], sH1[1], a0, a1);
            sGh[0][o] = a0; sGh[1][o] = a1;
        }
        for (int i = tid; i < 600; i += 256){
            int r = i / 300, o = i - r*300;
            sGi1[r][o] = g_GI1[((size_t)t*BATCH + b0 + r)*300 + o];
        }
        __syncthreads();
        // B: h1n
        for (int i = tid; i < 200; i += 256){
            int r = i / 100, d = i - r*100;
            float rr = sigm(sGi1[r][d]       + sGh[r][d]);
            float zz = sigm(sGi1[r][DIM+d]   + sGh[r][DIM+d]);
            float nn = tanhf(sGi1[r][2*DIM+d] + rr*sGh[r][2*DIM+d]);
            sH1n[r][d] = (1.f - zz)*nn + zz*sH1[r][d];
        }
        __syncthreads();
        // C: gi2 = Wih2@h1n, gh2 = Whh2@h2 (global weights, 2-row tiling)
        for (int i = tid; i < 600; i += 256){
            if (i < 300){
                int o = i;
                float a0 = sb2i[o], a1 = sb2i[o];
                dot2g(Wih2 + o*DIM, sH1n[0], sH1n[1], a0, a1);
                sGi2[0][o] = a0; sGi2[1][o] = a1;
            } else {
                int o = i - 300;
                float a0 = sb2h[o], a1 = sb2h[o];
                dot2g(Whh2 + o*DIM, sH2[0], sH2[1], a0, a1);
                sGh2[0][o] = a0; sGh2[1][o] = a1;
            }
        }
        __syncthreads();
        // D: g2
        for (int i = tid; i < 200; i += 256){
            int r = i / 100, d = i - r*100;
            float rr = sigm(sGi2[r][d]       + sGh2[r][d]);
            float zz = sigm(sGi2[r][DIM+d]   + sGh2[r][DIM+d]);
            float nn = tanhf(sGi2[r][2*DIM+d] + rr*sGh2[r][2*DIM+d]);
            sG2[r][d] = (1.f - zz)*nn + zz*sH2[r][d];
        }
        __syncthreads();
        // E: Kt0 for g2 (smem Wquery), gather states, load qtw
        for (int o = tid; o < DIM; o += 256){
            float a0 = sbq[o], a1 = sbq[o];
            dot2s(sWq + o*DIM, sG2[0], sG2[1], a0, a1);
            sKt0[0][o] = tanhf(a0); sKt0[1][o] = tanhf(a1);
        }
        for (int i = tid; i < 2200; i += 256){
            int r = i / 1100, rem = i - r*1100, s = rem / 100, d = rem - s*100;
            float v;
            if (s == 0) v = sG2[r][d];
            else {
                int src = (t > RKN) ? g_top[((size_t)t*BATCH + b0 + r)*RKN + (s-1)] : (s-1);
                if (d == 0) sSrc[r][s-1] = src;
                v = g_HIST[((size_t)(b0+r)*SEQ + src)*DIM + d];
            }
            sSt[r][s*DIM + d] = v;
        }
        if (tid < 10) sQtw[tid/5][tid%5] = g_qtw[((size_t)t*BATCH + b0 + tid/5)*5 + (tid%5)];
        __syncthreads();
        // F: og (55 x 2) + ktw0 (2), warp-per-task
        {
            int w = tid >> 5, lane = tid & 31;
            for (int task = w; task < 112; task += 8){
                if (task < 110){
                    int r = task / 55, rem = task - r*55, q = rem / 11, s = rem - q*11;
                    const float* qcp = g_qc + ((size_t)(t*BATCH + b0 + r))*(5*DIM) + q*DIM;
                    float part = 0.f;
                    for (int d = lane; d < DIM; d += 32) part += __ldg(&qcp[d]) * sSt[r][s*DIM + d];
                    part = wredsum(part);
                    if (lane == 0) sOg[r][rem] = part;
                } else {
                    int r = task - 110;
                    float part = 0.f;
                    for (int d = lane; d < DIM; d += 32) part += sKt0[r][d] * sWk[d];
                    part = wredsum(part);
                    if (lane == 0) sKtw0[r] = part;
                }
            }
        }
        __syncthreads();
        // G1: softmax
        if (tid < 10){
            int r = tid / 5, q = tid - r*5;
            float bw0 = sBW0, qt = sQtw[r][q];
            float tmp[11]; float mx = -INFINITY;
#pragma unroll
            for (int s = 0; s < 11; s++){
                bool valid = (s == 0) || (t > RKN) || ((s-1) < t);
                float ktw = (s == 0) ? sKtw0[r] : sCache[r][sSrc[r][s-1]];
                float v = valid ? (qt + ktw + bw0) : NEGV;
                tmp[s] = v; mx = fmaxf(mx, v);
            }
            float se = 0.f, acc = 0.f;
#pragma unroll
            for (int s = 0; s < 11; s++){
                float e = expf(tmp[s] - mx);
                se += e; acc += e * sOg[r][q*11 + s];
            }
            sP[r][q] = acc / se;
        }
        __syncthreads();
        // G2: output + state updates
        for (int i = tid; i < 200; i += 256){
            int r = i / 100, d = i - r*100;
            sH1[r][d] = sH1n[r][d];
            if (t > 0){
                sH2[r][d] = sG2[r][d];
                g_HIST[((size_t)(b0+r)*SEQ + t)*DIM + d] = sG2[r][d];
            }
        }
        if (tid < 2){
            float p = sP[tid][0] + sP[tid][1] + sP[tid][2] + sP[tid][3] + sP[tid][4];
            int col = (t == 0) ? 0 : (t + 1);
            out[(b0 + tid)*SEQ + col] = p;
            if (t > 0) sCache[tid][t] = sKtw0[tid];
        }
        __syncthreads();
    }
}

// ---------------- launch ----------------
extern "C" void kernel_launch(void* const* d_in, const int* in_sizes, int n_in,
                              void* d_out, int out_size){
    const float* Eq     = (const float*)d_in[0];
    const float* Ec     = (const float*)d_in[1];
    const float* Er     = (const float*)d_in[2];
    const float* Wih1   = (const float*)d_in[3];
    const float* Whh1   = (const float*)d_in[4];
    const float* bih1   = (const float*)d_in[5];
    const float* bhh1   = (const float*)d_in[6];
    const float* Wih2   = (const float*)d_in[7];
    const float* Whh2   = (const float*)d_in[8];
    const float* bih2   = (const float*)d_in[9];
    const float* bhh2   = (const float*)d_in[10];
    const float* Wagg   = (const float*)d_in[11];
    const float* bagg   = (const float*)d_in[12];
    const float* Wlast  = (const float*)d_in[13];
    const float* blast  = (const float*)d_in[14];
    const float* Wquery = (const float*)d_in[15];
    const float* bquery = (const float*)d_in[16];
    const float* Wkey   = (const float*)d_in[17];
    const float* bkey   = (const float*)d_in[18];
    const float* WW     = (const float*)d_in[19];
    const float* bW     = (const float*)d_in[20];
    const float* h1i    = (const float*)d_in[21];
    const float* h2i    = (const float*)d_in[22];
    const int* question = (const int*)d_in[23];
    const int* response = (const int*)d_in[24];
    const int* maskp    = (const int*)d_in[25];
    const int* qnb      = (const int*)d_in[26];
    const int* snb      = (const int*)d_in[27];
    const int* cidx     = (const int*)d_in[28];
    const void* cmask   = d_in[29];
    float* out = (float*)d_out;

    cudaFuncSetAttribute(k_scan, cudaFuncAttributeMaxDynamicSharedMemorySize, 160000);

    k_detect<<<1, 32>>>((const unsigned char*)cmask);
    k_qemb<<<2048, 256>>>(Eq, question);
    k_init<<<1024, 256>>>(out);
    k_gmat<<<dim3(4, BATCH), 256>>>();
    {
        int nwarp = 116*BATCH;
        int nb = (nwarp + 7) / 8;
        k_topk<<<nb, 256>>>();
    }
    k_qc<<<TSTEPS*BATCH, 128>>>(Ec, question, cidx, cmask, Wkey, bkey, WW);
    k_aggall<<<TSTEPS*BATCH, 128>>>(Eq, Ec, question, maskp, qnb, snb, Wagg, bagg, Wlast, blast);
    k_gier<<<3, 256>>>(Wih1, bih1, Er);
    k_gi1<<<dim3(TSTEPS, 2), 256>>>(Wih1, response);
    k_scan<<<BATCH/2, 256, 160000>>>(Whh1, bhh1, Wih2, bih2, Whh2, bhh2,
                                     Wquery, bquery, WW, bW, h1i, h2i, out);
}

// round 6
// speedup vs baseline: 4.8494x; 1.6158x over previous
#include <cuda_runtime.h>
#include <math.h>
#include <stdint.h>

#define BATCH 128
#define SEQ   128
#define DIM   100
#define QNB   4
#define SNB   4
#define KCN   4
#define RKN   10
#define TSTEPS 127
#define NEGV  -1000000000.0f

// ---------------- device scratch (no allocations) ----------------
__device__ float g_Qemb[BATCH*SEQ*DIM];
__device__ float g_G[(size_t)BATCH*SEQ*SEQ];
__device__ int   g_top[TSTEPS*BATCH*RKN];
__device__ float g_qc[(size_t)TSTEPS*BATCH*5*DIM];
__device__ float g_qtw[TSTEPS*BATCH*5];
__device__ float g_EMB[(size_t)TSTEPS*BATCH*DIM];
__device__ float g_GI1[(size_t)TSTEPS*BATCH*300];
__device__ float g_gier[2*300];
__device__ float g_G2ALL[(size_t)TSTEPS*BATCH*DIM];   // g2 for every (t,b)
__device__ float g_KTW[TSTEPS*BATCH];                 // <tanh(Wq g2 + bq), Wk>
__device__ float g_kz;                                // same for zero state
__device__ int   g_cm_mode;

// ---------------- helpers ----------------
__device__ __forceinline__ float sigm(float x){ return 1.f/(1.f+expf(-x)); }

__device__ __forceinline__ float wredsum(float v){
#pragma unroll
    for (int o = 16; o; o >>= 1) v += __shfl_xor_sync(0xFFFFFFFFu, v, o);
    return v;
}

template<int N4>
__device__ __forceinline__ float dotw(const float* __restrict__ w, const float* x){
    const float4* w4 = reinterpret_cast<const float4*>(w);
    float acc = 0.f;
#pragma unroll
    for (int i = 0; i < N4; i++){
        float4 wv = __ldg(w4+i);
        acc = fmaf(wv.x, x[4*i+0], acc);
        acc = fmaf(wv.y, x[4*i+1], acc);
        acc = fmaf(wv.z, x[4*i+2], acc);
        acc = fmaf(wv.w, x[4*i+3], acc);
    }
    return acc;
}

// two-vector dot against one weight row, weight in SMEM
__device__ __forceinline__ void dot2s(const float* w, const float* x0, const float* x1,
                                      float& a0, float& a1){
    const float4* w4 = (const float4*)w;
    const float4* p0 = (const float4*)x0;
    const float4* p1 = (const float4*)x1;
#pragma unroll
    for (int i = 0; i < 25; i++){
        float4 wv = w4[i];
        float4 u = p0[i], v = p1[i];
        a0 = fmaf(wv.x,u.x,a0); a0 = fmaf(wv.y,u.y,a0); a0 = fmaf(wv.z,u.z,a0); a0 = fmaf(wv.w,u.w,a0);
        a1 = fmaf(wv.x,v.x,a1); a1 = fmaf(wv.y,v.y,a1); a1 = fmaf(wv.z,v.z,a1); a1 = fmaf(wv.w,v.w,a1);
    }
}

// two-vector dot against one weight row, weight in GMEM
__device__ __forceinline__ void dot2g(const float* __restrict__ w, const float* x0, const float* x1,
                                      float& a0, float& a1){
    const float4* w4 = (const float4*)w;
    const float4* p0 = (const float4*)x0;
    const float4* p1 = (const float4*)x1;
#pragma unroll
    for (int i = 0; i < 25; i++){
        float4 wv = __ldg(w4+i);
        float4 u = p0[i], v = p1[i];
        a0 = fmaf(wv.x,u.x,a0); a0 = fmaf(wv.y,u.y,a0); a0 = fmaf(wv.z,u.z,a0); a0 = fmaf(wv.w,u.w,a0);
        a1 = fmaf(wv.x,v.x,a1); a1 = fmaf(wv.y,v.y,a1); a1 = fmaf(wv.z,v.z,a1); a1 = fmaf(wv.w,v.w,a1);
    }
}

// four-vector dot, weight in GMEM, x in SMEM
__device__ __forceinline__ void dot4(const float* __restrict__ w,
        const float* x0, const float* x1, const float* x2, const float* x3,
        float& a0, float& a1, float& a2, float& a3){
    const float4* w4 = (const float4*)w;
    const float4* p0 = (const float4*)x0;
    const float4* p1 = (const float4*)x1;
    const float4* p2 = (const float4*)x2;
    const float4* p3 = (const float4*)x3;
#pragma unroll
    for (int i = 0; i < 25; i++){
        float4 wv = __ldg(w4+i);
        float4 u0 = p0[i], u1 = p1[i], u2 = p2[i], u3 = p3[i];
        a0 = fmaf(wv.x,u0.x,a0); a0 = fmaf(wv.y,u0.y,a0); a0 = fmaf(wv.z,u0.z,a0); a0 = fmaf(wv.w,u0.w,a0);
        a1 = fmaf(wv.x,u1.x,a1); a1 = fmaf(wv.y,u1.y,a1); a1 = fmaf(wv.z,u1.z,a1); a1 = fmaf(wv.w,u1.w,a1);
        a2 = fmaf(wv.x,u2.x,a2); a2 = fmaf(wv.y,u2.y,a2); a2 = fmaf(wv.z,u2.z,a2); a2 = fmaf(wv.w,u2.w,a2);
        a3 = fmaf(wv.x,u3.x,a3); a3 = fmaf(wv.y,u3.y,a3); a3 = fmaf(wv.z,u3.z,a3); a3 = fmaf(wv.w,u3.w,a3);
    }
}

// ---------------- one-time kernels ----------------
__global__ void k_detect(const unsigned char* __restrict__ cm){
    if (blockIdx.x == 0 && threadIdx.x == 0){
        int intOK = 1, fltOK = 1;
        for (int g = 0; g < 1000; g++){
            uint32_t v = 0;
            v |= (uint32_t)cm[4*g+0];
            v |= (uint32_t)cm[4*g+1] << 8;
            v |= (uint32_t)cm[4*g+2] << 16;
            v |= (uint32_t)cm[4*g+3] << 24;
            if (!(v == 0u || v == 1u)) intOK = 0;
            if (!(v == 0u || v == 0x3F800000u)) fltOK = 0;
        }
        g_cm_mode = intOK ? 1 : (fltOK ? 2 : 0);
    }
}

__global__ void k_qemb(const float* __restrict__ Eq, const int* __restrict__ question){
    int n = BATCH*SEQ*DIM;
    for (int i = blockIdx.x*blockDim.x + threadIdx.x; i < n; i += gridDim.x*blockDim.x){
        int bs = i / DIM, d = i - bs*DIM;
        g_Qemb[i] = __ldg(&Eq[(size_t)question[bs]*DIM + d]);
    }
}

__global__ void k_init(float* __restrict__ out){
    int i = blockIdx.x*blockDim.x + threadIdx.x;
    if (i < BATCH*SEQ) out[i] = 0.f;
}

__global__ void k_kz(const float* __restrict__ bquery, const float* __restrict__ WW){
    float v = 0.f;
    for (int d = threadIdx.x; d < DIM; d += 32) v += tanhf(__ldg(&bquery[d])) * __ldg(&WW[DIM+d]);
    v = wredsum(v);
    if (threadIdx.x == 0) g_kz = v;
}

// Gram matrix, register-tiled 4x4; grid (4, 128), 256 threads
__global__ void __launch_bounds__(256) k_gmat(){
    int b = blockIdx.y;
    int i0 = blockIdx.x * 32;
    int tid = threadIdx.x;
    __shared__ __align__(16) float sQ[32*DIM];
    const float* Qb = g_Qemb + (size_t)b*SEQ*DIM;
    for (int i = tid; i < 32*DIM; i += 256){
        int r = i / DIM, d = i - r*DIM;
        sQ[i] = Qb[(size_t)(i0 + r)*DIM + d];
    }
    __syncthreads();
    int ti = (tid >> 5) * 4;
    int tj = (tid & 31) * 4;
    float acc[4][4];
#pragma unroll
    for (int a = 0; a < 4; a++)
#pragma unroll
        for (int c = 0; c < 4; c++) acc[a][c] = 0.f;
    const float4* qi0 = (const float4*)(sQ + (ti+0)*DIM);
    const float4* qi1 = (const float4*)(sQ + (ti+1)*DIM);
    const float4* qi2 = (const float4*)(sQ + (ti+2)*DIM);
    const float4* qi3 = (const float4*)(sQ + (ti+3)*DIM);
    const float4* qj0 = (const float4*)(Qb + (size_t)(tj+0)*DIM);
    const float4* qj1 = (const float4*)(Qb + (size_t)(tj+1)*DIM);
    const float4* qj2 = (const float4*)(Qb + (size_t)(tj+2)*DIM);
    const float4* qj3 = (const float4*)(Qb + (size_t)(tj+3)*DIM);
#pragma unroll
    for (int k = 0; k < 25; k++){
        float4 A0 = qi0[k], A1 = qi1[k], A2 = qi2[k], A3 = qi3[k];
        float4 B0 = __ldg(qj0+k), B1 = __ldg(qj1+k), B2 = __ldg(qj2+k), B3 = __ldg(qj3+k);
#define GM(a,c,A,B) acc[a][c]=fmaf(A.x,B.x,acc[a][c]); acc[a][c]=fmaf(A.y,B.y,acc[a][c]); acc[a][c]=fmaf(A.z,B.z,acc[a][c]); acc[a][c]=fmaf(A.w,B.w,acc[a][c]);
        GM(0,0,A0,B0) GM(0,1,A0,B1) GM(0,2,A0,B2) GM(0,3,A0,B3)
        GM(1,0,A1,B0) GM(1,1,A1,B1) GM(1,2,A1,B2) GM(1,3,A1,B3)
        GM(2,0,A2,B0) GM(2,1,A2,B1) GM(2,2,A2,B2) GM(2,3,A2,B3)
        GM(3,0,A3,B0) GM(3,1,A3,B1) GM(3,2,A3,B2) GM(3,3,A3,B3)
#undef GM
    }
    float* Gb = g_G + (size_t)b*SEQ*SEQ;
#pragma unroll
    for (int a = 0; a < 4; a++)
#pragma unroll
        for (int c = 0; c < 4; c++)
            Gb[(size_t)(i0+ti+a)*SEQ + (tj+c)] = acc[a][c];
}

// top-10 with jax tie-break (lower index wins), t in [11,126]
__global__ void k_topk(){
    int wg   = blockIdx.x*(blockDim.x >> 5) + (threadIdx.x >> 5);
    int lane = threadIdx.x & 31;
    if (wg >= 116*BATCH) return;
    int t = 11 + wg / BATCH;
    int b = wg % BATCH;
    const float* Gb = g_G + (size_t)b*SEQ*SEQ;
    unsigned selm = 0;
    for (int r = 0; r < RKN; r++){
        float bv = -INFINITY; int bi = SEQ;
#pragma unroll
        for (int m = 0; m < 4; m++){
            int s = lane + 32*m;
            if (s < t && !((selm >> m) & 1u)){
                float v = __ldg(&Gb[(size_t)s*SEQ + (t+1)]);
                if (v > bv || (v == bv && s < bi)){ bv = v; bi = s; }
            }
        }
#pragma unroll
        for (int o = 16; o; o >>= 1){
            float ov = __shfl_xor_sync(0xFFFFFFFFu, bv, o);
            int   oi = __shfl_xor_sync(0xFFFFFFFFu, bi, o);
            if (ov > bv || (ov == bv && oi < bi)){ bv = ov; bi = oi; }
        }
        if ((bi & 31) == lane) selm |= 1u << (bi >> 5);
        if (lane == 0) g_top[((size_t)t*BATCH + b)*RKN + r] = bi;
    }
}

// qc[t,b] rows and qtw[t,b][q]
__global__ void k_qc(const float* __restrict__ Ec, const int* __restrict__ question,
                     const int* __restrict__ concept_idx, const void* __restrict__ cmask,
                     const float* __restrict__ W_key, const float* __restrict__ b_key,
                     const float* __restrict__ W_W){
    int t = blockIdx.x / BATCH, b = blockIdx.x % BATCH;
    int tid = threadIdx.x;
    __shared__ __align__(16) float sqc[5*DIM];
    __shared__ __align__(16) float sQt[5*DIM];
    int qn = question[b*SEQ + t + 1];
    int mode = g_cm_mode;
    for (int i = tid; i < 5*DIM; i += blockDim.x){
        int q = i / DIM, d = i - q*DIM;
        float v;
        if (q == 0){
            v = g_Qemb[((size_t)b*SEQ + t + 1)*DIM + d];
        } else {
            int fi = qn*KCN + (q - 1);
            bool mk;
            if (mode == 1)      mk = ((const int*)cmask)[fi] != 0;
            else if (mode == 2) mk = ((const float*)cmask)[fi] != 0.f;
            else                mk = ((const unsigned char*)cmask)[fi] != 0;
            int ci = __ldg(&concept_idx[fi]);
            v = mk ? __ldg(&Ec[(size_t)ci*DIM + d]) : 0.f;
        }
        sqc[i] = v;
        g_qc[((size_t)(t*BATCH + b))*(5*DIM) + i] = v;
    }
    __syncthreads();
    for (int i = tid; i < 5*DIM; i += blockDim.x){
        int q = i / DIM, o = i - q*DIM;
        sQt[i] = tanhf(dotw<25>(W_key + o*DIM, sqc + q*DIM) + __ldg(&b_key[o]));
    }
    __syncthreads();
    int w = tid >> 5, lane = tid & 31;
    for (int q = w; q < 5; q += (blockDim.x >> 5)){
        float part = 0.f;
        for (int d = lane; d < DIM; d += 32) part += sQt[q*DIM + d] * __ldg(&W_W[d]);
        part = wredsum(part);
        if (lane == 0) g_qtw[((size_t)t*BATCH + b)*5 + q] = part;
    }
}

// aggregate(q_t) for ALL (t,b), or Eq copy when mask==0
__global__ void __launch_bounds__(128) k_aggall(
    const float* __restrict__ Eq, const float* __restrict__ Ec,
    const int* __restrict__ question, const int* __restrict__ mask,
    const int* __restrict__ qnb, const int* __restrict__ snb,
    const float* __restrict__ Wagg, const float* __restrict__ bagg,
    const float* __restrict__ Wlast, const float* __restrict__ blast)
{
    int tb = blockIdx.x;
    int t = tb >> 7, b = tb & 127;
    int tid = threadIdx.x;
    int q_t = question[b*SEQ + t];
    float* dst = g_EMB + (size_t)tb*DIM;
    if (mask[b*SEQ + t] == 0){
        for (int d = tid; d < DIM; d += 128) dst[d] = __ldg(&Eq[(size_t)q_t*DIM + d]);
        return;
    }
    __shared__ __align__(16) float sE1[4*DIM], sE2[16*DIM], sU[16*DIM], sV[16*DIM];
    __shared__ __align__(16) float sV1[4*DIM], sT4[4*DIM], sW1[4*DIM];
    __shared__ __align__(16) float vA[DIM], vB[DIM], vC[DIM];
    __shared__ int sN1[4], sN2[16], sN3[64];

    if (tid < QNB) sN1[tid] = __ldg(&qnb[q_t*QNB + tid]);
    __syncthreads();
    if (tid < 16) sN2[tid] = __ldg(&snb[sN1[tid >> 2]*SNB + (tid & 3)]);
    __syncthreads();
    if (tid < 64) sN3[tid] = __ldg(&qnb[sN2[tid >> 2]*QNB + (tid & 3)]);
    for (int i = tid; i < 4*DIM; i += 128){
        int r = i / DIM, d = i - r*DIM;
        sE1[i] = __ldg(&Ec[(size_t)sN1[r]*DIM + d]);
    }
    __syncthreads();
    for (int i = tid; i < 16*DIM; i += 128){
        int k = i / DIM, d = i - k*DIM;
        float e2v = __ldg(&Eq[(size_t)sN2[k]*DIM + d]);
        float s3 = __ldg(&Ec[(size_t)sN3[4*k+0]*DIM + d]) + __ldg(&Ec[(size_t)sN3[4*k+1]*DIM + d])
                 + __ldg(&Ec[(size_t)sN3[4*k+2]*DIM + d]) + __ldg(&Ec[(size_t)sN3[4*k+3]*DIM + d]);
        sE2[i] = e2v;
        sU[i]  = e2v + 0.25f*s3;
    }
    __syncthreads();
    // stage i=0
    for (int task = tid; task < 4*DIM; task += 128){
        int o = task >> 2, kb = (task & 3) * 4;
        float a0=0.f,a1=0.f,a2=0.f,a3=0.f;
        dot4(Wagg + 2*DIM*DIM + o*DIM, sU+(kb+0)*DIM, sU+(kb+1)*DIM, sU+(kb+2)*DIM, sU+(kb+3)*DIM, a0,a1,a2,a3);
        float bb = __ldg(&bagg[2*DIM + o]);
        sV[(kb+0)*DIM+o] = tanhf(a0+bb);
        sV[(kb+1)*DIM+o] = tanhf(a1+bb);
        sV[(kb+2)*DIM+o] = tanhf(a2+bb);
        sV[(kb+3)*DIM+o] = tanhf(a3+bb);
    }
    for (int i = tid; i < 4*DIM; i += 128){
        int r = i / DIM, d = i - r*DIM;
        sT4[i] = sE1[i] + 0.25f*(sE2[(4*r+0)*DIM+d] + sE2[(4*r+1)*DIM+d]
                               + sE2[(4*r+2)*DIM+d] + sE2[(4*r+3)*DIM+d]);
    }
    for (int d = tid; d < DIM; d += 128)
        vA[d] = __ldg(&Eq[(size_t)q_t*DIM + d]) + 0.25f*(sE1[d] + sE1[DIM+d] + sE1[2*DIM+d] + sE1[3*DIM+d]);
    __syncthreads();
    for (int o = tid; o < DIM; o += 128){
        float a0=0.f,a1=0.f,a2=0.f,a3=0.f;
        dot4(Wagg + DIM*DIM + o*DIM, sT4, sT4+DIM, sT4+2*DIM, sT4+3*DIM, a0,a1,a2,a3);
        float bb = __ldg(&bagg[DIM + o]);
        sV1[o] = tanhf(a0+bb); sV1[DIM+o] = tanhf(a1+bb);
        sV1[2*DIM+o] = tanhf(a2+bb); sV1[3*DIM+o] = tanhf(a3+bb);
        vB[o] = tanhf(dotw<25>(Wagg + o*DIM, vA) + __ldg(&bagg[o]));
    }
    __syncthreads();
    // stage i=1
    for (int i = tid; i < 4*DIM; i += 128){
        int r = i / DIM, d = i - r*DIM;
        sT4[i] = sV1[i] + 0.25f*(sV[(4*r+0)*DIM+d] + sV[(4*r+1)*DIM+d]
                               + sV[(4*r+2)*DIM+d] + sV[(4*r+3)*DIM+d]);
    }
    for (int d = tid; d < DIM; d += 128)
        vA[d] = vB[d] + 0.25f*(sV1[d] + sV1[DIM+d] + sV1[2*DIM+d] + sV1[3*DIM+d]);
    __syncthreads();
    for (int o = tid; o < DIM; o += 128){
        float a0=0.f,a1=0.f,a2=0.f,a3=0.f;
        dot4(Wagg + DIM*DIM + o*DIM, sT4, sT4+DIM, sT4+2*DIM, sT4+3*DIM, a0,a1,a2,a3);
        float bb = __ldg(&bagg[DIM + o]);
        sW1[o] = tanhf(a0+bb); sW1[DIM+o] = tanhf(a1+bb);
        sW1[2*DIM+o] = tanhf(a2+bb); sW1[3*DIM+o] = tanhf(a3+bb);
        vC[o] = tanhf(dotw<25>(Wagg + o*DIM, vA) + __ldg(&bagg[o]));
    }
    __syncthreads();
    // stage i=2
    for (int d = tid; d < DIM; d += 128)
        vA[d] = vC[d] + 0.25f*(sW1[d] + sW1[DIM+d] + sW1[2*DIM+d] + sW1[3*DIM+d]);
    __syncthreads();
    for (int o = tid; o < DIM; o += 128)
        vB[o] = tanhf(dotw<25>(Wagg + o*DIM, vA) + __ldg(&bagg[o]));
    __syncthreads();
    for (int o = tid; o < DIM; o += 128)
        dst[o] = tanhf(dotw<25>(Wlast + o*DIM, vB) + __ldg(&blast[o]));
}

// gier[r][o] = Wih1[o, D:2D] @ Er[r] + bih1[o]
__global__ void k_gier(const float* __restrict__ Wih1, const float* __restrict__ bih1,
                       const float* __restrict__ Er){
    int idx = blockIdx.x*blockDim.x + threadIdx.x;
    if (idx >= 600) return;
    int r = idx / 300, o = idx - r*300;
    g_gier[idx] = dotw<25>(Wih1 + o*2*DIM + DIM, Er + r*DIM) + __ldg(&bih1[o]);
}

// gi1[t,b,o] = Wih1[o,:D] @ emb[t,b] + gier[r_t]; grid (TSTEPS, 2)
__global__ void __launch_bounds__(256) k_gi1(const float* __restrict__ Wih1,
                                             const int* __restrict__ response){
    int t = blockIdx.x, zb = blockIdx.y;
    int tid = threadIdx.x;
    __shared__ __align__(16) float sE[DIM*64];   // [d][b]
    __shared__ int sRt[64];
    for (int i = tid; i < 64*DIM; i += 256){
        int bb = i / DIM, d = i - bb*DIM;
        sE[d*64 + bb] = g_EMB[((size_t)t*BATCH + zb*64 + bb)*DIM + d];
    }
    if (tid < 64) sRt[tid] = response[(zb*64 + tid)*SEQ + t];
    __syncthreads();
    for (int tt = tid; tt < 600; tt += 256){
        int ro = (tt >> 3) * 4;
        int bo = (tt & 7) * 8;
        float acc[4][8];
#pragma unroll
        for (int i = 0; i < 4; i++)
#pragma unroll
            for (int j = 0; j < 8; j++) acc[i][j] = 0.f;
        for (int k = 0; k < DIM; k++){
            float w0 = __ldg(&Wih1[(size_t)(ro+0)*2*DIM + k]);
            float w1 = __ldg(&Wih1[(size_t)(ro+1)*2*DIM + k]);
            float w2 = __ldg(&Wih1[(size_t)(ro+2)*2*DIM + k]);
            float w3 = __ldg(&Wih1[(size_t)(ro+3)*2*DIM + k]);
            const float* e = sE + k*64 + bo;
#pragma unroll
            for (int j = 0; j < 8; j++){
                float ev = e[j];
                acc[0][j] = fmaf(w0, ev, acc[0][j]);
                acc[1][j] = fmaf(w1, ev, acc[1][j]);
                acc[2][j] = fmaf(w2, ev, acc[2][j]);
                acc[3][j] = fmaf(w3, ev, acc[3][j]);
            }
        }
#pragma unroll
        for (int i = 0; i < 4; i++)
#pragma unroll
            for (int j = 0; j < 8; j++){
                int b = zb*64 + bo + j;
                int o = ro + i;
                g_GI1[((size_t)t*BATCH + b)*300 + o] = acc[i][j] + g_gier[sRt[bo+j]*300 + o];
            }
    }
}

// ---------------- persistent GRU-only scan: 64 blocks, 2 batch rows each ----------------
__global__ void __launch_bounds__(256) k_scan(
    const float* __restrict__ Whh1, const float* __restrict__ bhh1,
    const float* __restrict__ Wih2, const float* __restrict__ bih2,
    const float* __restrict__ Whh2, const float* __restrict__ bhh2,
    const float* __restrict__ h1i, const float* __restrict__ h2i)
{
    extern __shared__ __align__(16) float sWhh1[];   // 30000 floats
    __shared__ __align__(16) float sH1[2][DIM], sH1n[2][DIM], sH2[2][DIM];
    __shared__ __align__(16) float sGh[2][300], sGi1[2][300], sGi2[2][300], sGh2[2][300];
    __shared__ float sb1[300], sb2i[300], sb2h[300];

    int tid = threadIdx.x;
    int b0 = blockIdx.x*2;

    for (int i = tid; i < 30000; i += 256) sWhh1[i] = Whh1[i];
    for (int i = tid; i < 300; i += 256){ sb1[i]=bhh1[i]; sb2i[i]=bih2[i]; sb2h[i]=bhh2[i]; }
    for (int i = tid; i < DIM; i += 256){
        sH1[0][i] = h1i[b0*DIM+i];     sH1[1][i] = h1i[(b0+1)*DIM+i];
        sH2[0][i] = h2i[b0*DIM+i];     sH2[1][i] = h2i[(b0+1)*DIM+i];
    }
    __syncthreads();

    for (int t = 0; t < TSTEPS; t++){
        // A: gh1 = Whh1@h1 + bhh1 (smem weights), load gi1 rows
        for (int o = tid; o < 300; o += 256){
            float a0 = sb1[o], a1 = sb1[o];
            dot2s(sWhh1 + o*DIM, sH1[0], sH1[1], a0, a1);
            sGh[0][o] = a0; sGh[1][o] = a1;
        }
        for (int i = tid; i < 600; i += 256){
            int r = i / 300, o = i - r*300;
            sGi1[r][o] = g_GI1[((size_t)t*BATCH + b0 + r)*300 + o];
        }
        __syncthreads();
        // B: h1n
        for (int i = tid; i < 200; i += 256){
            int r = i / 100, d = i - r*100;
            float rr = sigm(sGi1[r][d]       + sGh[r][d]);
            float zz = sigm(sGi1[r][DIM+d]   + sGh[r][DIM+d]);
            float nn = tanhf(sGi1[r][2*DIM+d] + rr*sGh[r][2*DIM+d]);
            sH1n[r][d] = (1.f - zz)*nn + zz*sH1[r][d];
        }
        __syncthreads();
        // C: gi2 = Wih2@h1n, gh2 = Whh2@h2 (global weights, 2-row tiling)
        for (int i = tid; i < 600; i += 256){
            if (i < 300){
                int o = i;
                float a0 = sb2i[o], a1 = sb2i[o];
                dot2g(Wih2 + o*DIM, sH1n[0], sH1n[1], a0, a1);
                sGi2[0][o] = a0; sGi2[1][o] = a1;
            } else {
                int o = i - 300;
                float a0 = sb2h[o], a1 = sb2h[o];
                dot2g(Whh2 + o*DIM, sH2[0], sH2[1], a0, a1);
                sGh2[0][o] = a0; sGh2[1][o] = a1;
            }
        }
        __syncthreads();
        // D: g2, store to g_G2ALL, state updates
        for (int i = tid; i < 200; i += 256){
            int r = i / 100, d = i - r*100;
            float rr = sigm(sGi2[r][d]       + sGh2[r][d]);
            float zz = sigm(sGi2[r][DIM+d]   + sGh2[r][DIM+d]);
            float nn = tanhf(sGi2[r][2*DIM+d] + rr*sGh2[r][2*DIM+d]);
            float g2 = (1.f - zz)*nn + zz*sH2[r][d];
            g_G2ALL[((size_t)t*BATCH + b0 + r)*DIM + d] = g2;
            sH1[r][d] = sH1n[r][d];
            if (t > 0) sH2[r][d] = g2;
        }
        __syncthreads();
    }
}

// ---------------- parallel post-passes ----------------
// ktw[t,b] = <tanh(Wq @ g2[t,b] + bq), Wk>
__global__ void __launch_bounds__(128) k_ktw(const float* __restrict__ Wquery,
                                             const float* __restrict__ bquery,
                                             const float* __restrict__ WW){
    int tb = blockIdx.x;
    int tid = threadIdx.x;
    __shared__ __align__(16) float sg2[DIM];
    __shared__ float sred[DIM];
    const float* g2 = g_G2ALL + (size_t)tb*DIM;
    for (int d = tid; d < DIM; d += 128) sg2[d] = g2[d];
    __syncthreads();
    for (int o = tid; o < DIM; o += 128)
        sred[o] = tanhf(dotw<25>(Wquery + o*DIM, sg2) + __ldg(&bquery[o])) * __ldg(&WW[DIM+o]);
    __syncthreads();
    if (tid < 32){
        float v = 0.f;
        for (int o = tid; o < DIM; o += 32) v += sred[o];
        v = wredsum(v);
        if (tid == 0) g_KTW[tb] = v;
    }
}

// full predict for one (t,b): gather states, og dots, softmax, output
__global__ void __launch_bounds__(64) k_predict(const float* __restrict__ bW,
                                                float* __restrict__ out){
    int tb = blockIdx.x;
    int t = tb >> 7, b = tb & 127;
    int tid = threadIdx.x;
    __shared__ __align__(16) float sSt[11*DIM];
    __shared__ float sOg[55], sKtw[11], sQtw[5], sP[5];
    __shared__ int sSrc[11];

    if (tid < 11){
        int src = 0;
        float k;
        if (tid == 0){
            k = g_KTW[tb];
        } else {
            src = (t > RKN) ? g_top[((size_t)t*BATCH + b)*RKN + (tid-1)] : (tid-1);
            k = (src == 0) ? g_kz : g_KTW[(size_t)src*BATCH + b];
        }
        sSrc[tid] = src;
        sKtw[tid] = k;
    }
    if (tid >= 11 && tid < 16) sQtw[tid-11] = g_qtw[(size_t)tb*5 + (tid-11)];
    __syncthreads();
    for (int i = tid; i < 11*DIM; i += 64){
        int s = i / DIM, d = i - s*DIM;
        float v;
        if (s == 0) v = g_G2ALL[(size_t)tb*DIM + d];
        else {
            int src = sSrc[s];
            v = (src == 0) ? 0.f : g_G2ALL[((size_t)src*BATCH + b)*DIM + d];
        }
        sSt[i] = v;
    }
    __syncthreads();
    if (tid < 55){
        int q = tid / 11, s = tid - q*11;
        const float4* a = (const float4*)(g_qc + (size_t)tb*(5*DIM) + q*DIM);
        const float4* xx = (const float4*)(sSt + s*DIM);
        float acc = 0.f;
#pragma unroll
        for (int i = 0; i < 25; i++){
            float4 w = __ldg(a+i), u = xx[i];
            acc = fmaf(w.x,u.x,acc); acc = fmaf(w.y,u.y,acc);
            acc = fmaf(w.z,u.z,acc); acc = fmaf(w.w,u.w,acc);
        }
        sOg[tid] = acc;
    }
    __syncthreads();
    if (tid < 5){
        int q = tid;
        float bw0 = __ldg(&bW[0]);
        float qt = sQtw[q];
        float tmp[11]; float mx = -INFINITY;
#pragma unroll
        for (int s = 0; s < 11; s++){
            bool valid = (s == 0) || (t > RKN) || ((s-1) < t);
            float v = valid ? (qt + sKtw[s] + bw0) : NEGV;
            tmp[s] = v; mx = fmaxf(mx, v);
        }
        float se = 0.f, acc = 0.f;
#pragma unroll
        for (int s = 0; s < 11; s++){
            float e = expf(tmp[s] - mx);
            se += e; acc += e * sOg[q*11 + s];
        }
        sP[q] = acc / se;
    }
    __syncthreads();
    if (tid == 0){
        float p = sP[0] + sP[1] + sP[2] + sP[3] + sP[4];
        int col = (t == 0) ? 0 : (t + 1);
        out[b*SEQ + col] = p;
    }
}

// ---------------- launch ----------------
extern "C" void kernel_launch(void* const* d_in, const int* in_sizes, int n_in,
                              void* d_out, int out_size){
    const float* Eq     = (const float*)d_in[0];
    const float* Ec     = (const float*)d_in[1];
    const float* Er     = (const float*)d_in[2];
    const float* Wih1   = (const float*)d_in[3];
    const float* Whh1   = (const float*)d_in[4];
    const float* bih1   = (const float*)d_in[5];
    const float* bhh1   = (const float*)d_in[6];
    const float* Wih2   = (const float*)d_in[7];
    const float* Whh2   = (const float*)d_in[8];
    const float* bih2   = (const float*)d_in[9];
    const float* bhh2   = (const float*)d_in[10];
    const float* Wagg   = (const float*)d_in[11];
    const float* bagg   = (const float*)d_in[12];
    const float* Wlast  = (const float*)d_in[13];
    const float* blast  = (const float*)d_in[14];
    const float* Wquery = (const float*)d_in[15];
    const float* bquery = (const float*)d_in[16];
    const float* Wkey   = (const float*)d_in[17];
    const float* bkey   = (const float*)d_in[18];
    const float* WW     = (const float*)d_in[19];
    const float* bW     = (const float*)d_in[20];
    const float* h1i    = (const float*)d_in[21];
    const float* h2i    = (const float*)d_in[22];
    const int* question = (const int*)d_in[23];
    const int* response = (const int*)d_in[24];
    const int* maskp    = (const int*)d_in[25];
    const int* qnb      = (const int*)d_in[26];
    const int* snb      = (const int*)d_in[27];
    const int* cidx     = (const int*)d_in[28];
    const void* cmask   = d_in[29];
    float* out = (float*)d_out;

    cudaFuncSetAttribute(k_scan, cudaFuncAttributeMaxDynamicSharedMemorySize, 122880);

    k_detect<<<1, 32>>>((const unsigned char*)cmask);
    k_qemb<<<2048, 256>>>(Eq, question);
    k_init<<<64, 256>>>(out);
    k_kz<<<1, 32>>>(bquery, WW);
    k_gmat<<<dim3(4, BATCH), 256>>>();
    {
        int nwarp = 116*BATCH;
        int nb = (nwarp + 7) / 8;
        k_topk<<<nb, 256>>>();
    }
    k_qc<<<TSTEPS*BATCH, 128>>>(Ec, question, cidx, cmask, Wkey, bkey, WW);
    k_aggall<<<TSTEPS*BATCH, 128>>>(Eq, Ec, question, maskp, qnb, snb, Wagg, bagg, Wlast, blast);
    k_gier<<<3, 256>>>(Wih1, bih1, Er);
    k_gi1<<<dim3(TSTEPS, 2), 256>>>(Wih1, response);
    k_scan<<<BATCH/2, 256, 120000>>>(Whh1, bhh1, Wih2, bih2, Whh2, bhh2, h1i, h2i);
    k_ktw<<<TSTEPS*BATCH, 128>>>(Wquery, bquery, WW);
    k_predict<<<TSTEPS*BATCH, 64>>>(bW, out);
}

// round 7
// speedup vs baseline: 6.6348x; 1.3682x over previous
#include <cuda_runtime.h>
#include <math.h>
#include <stdint.h>

#define BATCH 128
#define SEQ   128
#define DIM   100
#define QNB   4
#define SNB   4
#define KCN   4
#define RKN   10
#define TSTEPS 127
#define NEGV  -1000000000.0f

// ---------------- device scratch (no allocations) ----------------
__device__ float g_Qemb[BATCH*SEQ*DIM];
__device__ float g_G[(size_t)BATCH*SEQ*SEQ];
__device__ int   g_top[TSTEPS*BATCH*RKN];
__device__ float g_qc[(size_t)TSTEPS*BATCH*5*DIM];
__device__ float g_qtw[TSTEPS*BATCH*5];
__device__ float g_EMB[(size_t)TSTEPS*BATCH*DIM];
__device__ float g_GI1[(size_t)TSTEPS*BATCH*300];
__device__ float g_gier[2*300];
__device__ float g_H1N[(size_t)TSTEPS*BATCH*DIM];
__device__ float g_G2ALL[(size_t)TSTEPS*BATCH*DIM];
__device__ float g_KTW[TSTEPS*BATCH];
__device__ float g_kz;
__device__ int   g_cm_mode;
__device__ int   g_SYNC[64];

#define BAR1() asm volatile("bar.sync 1, 128;" ::: "memory")
#define BAR2() asm volatile("bar.sync 2, 128;" ::: "memory")

// ---------------- helpers ----------------
__device__ __forceinline__ float sigm(float x){ return 1.f/(1.f+expf(-x)); }

__device__ __forceinline__ float wredsum(float v){
#pragma unroll
    for (int o = 16; o; o >>= 1) v += __shfl_xor_sync(0xFFFFFFFFu, v, o);
    return v;
}

template<int N4>
__device__ __forceinline__ float dotw(const float* __restrict__ w, const float* x){
    const float4* w4 = reinterpret_cast<const float4*>(w);
    float acc = 0.f;
#pragma unroll
    for (int i = 0; i < N4; i++){
        float4 wv = __ldg(w4+i);
        acc = fmaf(wv.x, x[4*i+0], acc);
        acc = fmaf(wv.y, x[4*i+1], acc);
        acc = fmaf(wv.z, x[4*i+2], acc);
        acc = fmaf(wv.w, x[4*i+3], acc);
    }
    return acc;
}

__device__ __forceinline__ void dot2s(const float* w, const float* x0, const float* x1,
                                      float& a0, float& a1){
    const float4* w4 = (const float4*)w;
    const float4* p0 = (const float4*)x0;
    const float4* p1 = (const float4*)x1;
#pragma unroll
    for (int i = 0; i < 25; i++){
        float4 wv = w4[i];
        float4 u = p0[i], v = p1[i];
        a0 = fmaf(wv.x,u.x,a0); a0 = fmaf(wv.y,u.y,a0); a0 = fmaf(wv.z,u.z,a0); a0 = fmaf(wv.w,u.w,a0);
        a1 = fmaf(wv.x,v.x,a1); a1 = fmaf(wv.y,v.y,a1); a1 = fmaf(wv.z,v.z,a1); a1 = fmaf(wv.w,v.w,a1);
    }
}

__device__ __forceinline__ void dot2g(const float* __restrict__ w, const float* x0, const float* x1,
                                      float& a0, float& a1){
    const float4* w4 = (const float4*)w;
    const float4* p0 = (const float4*)x0;
    const float4* p1 = (const float4*)x1;
#pragma unroll
    for (int i = 0; i < 25; i++){
        float4 wv = __ldg(w4+i);
        float4 u = p0[i], v = p1[i];
        a0 = fmaf(wv.x,u.x,a0); a0 = fmaf(wv.y,u.y,a0); a0 = fmaf(wv.z,u.z,a0); a0 = fmaf(wv.w,u.w,a0);
        a1 = fmaf(wv.x,v.x,a1); a1 = fmaf(wv.y,v.y,a1); a1 = fmaf(wv.z,v.z,a1); a1 = fmaf(wv.w,v.w,a1);
    }
}

__device__ __forceinline__ void dot4(const float* __restrict__ w,
        const float* x0, const float* x1, const float* x2, const float* x3,
        float& a0, float& a1, float& a2, float& a3){
    const float4* w4 = (const float4*)w;
    const float4* p0 = (const float4*)x0;
    const float4* p1 = (const float4*)x1;
    const float4* p2 = (const float4*)x2;
    const float4* p3 = (const float4*)x3;
#pragma unroll
    for (int i = 0; i < 25; i++){
        float4 wv = __ldg(w4+i);
        float4 u0 = p0[i], u1 = p1[i], u2 = p2[i], u3 = p3[i];
        a0 = fmaf(wv.x,u0.x,a0); a0 = fmaf(wv.y,u0.y,a0); a0 = fmaf(wv.z,u0.z,a0); a0 = fmaf(wv.w,u0.w,a0);
        a1 = fmaf(wv.x,u1.x,a1); a1 = fmaf(wv.y,u1.y,a1); a1 = fmaf(wv.z,u1.z,a1); a1 = fmaf(wv.w,u1.w,a1);
        a2 = fmaf(wv.x,u2.x,a2); a2 = fmaf(wv.y,u2.y,a2); a2 = fmaf(wv.z,u2.z,a2); a2 = fmaf(wv.w,u2.w,a2);
        a3 = fmaf(wv.x,u3.x,a3); a3 = fmaf(wv.y,u3.y,a3); a3 = fmaf(wv.z,u3.z,a3); a3 = fmaf(wv.w,u3.w,a3);
    }
}

// ---------------- fused setup: qemb + detect + kz + gier + zeroing ----------------
__global__ void __launch_bounds__(256) k_pre(
    const float* __restrict__ Eq, const int* __restrict__ question,
    const unsigned char* __restrict__ cm,
    const float* __restrict__ bquery, const float* __restrict__ WW,
    const float* __restrict__ Wih1, const float* __restrict__ bih1,
    const float* __restrict__ Er, float* __restrict__ out)
{
    int gtid = blockIdx.x*256 + threadIdx.x;
    if (gtid < BATCH*SEQ) out[gtid] = 0.f;
    if (gtid < 64) g_SYNC[gtid] = 0;
    // detect: warp 0 of block 64
    if (gtid >= 16384 && gtid < 16416){
        int lane = gtid - 16384;
        int intOK = 1, fltOK = 1;
        for (int g = lane; g < 1000; g += 32){
            uint32_t v = 0;
            v |= (uint32_t)cm[4*g+0];
            v |= (uint32_t)cm[4*g+1] << 8;
            v |= (uint32_t)cm[4*g+2] << 16;
            v |= (uint32_t)cm[4*g+3] << 24;
            if (!(v == 0u || v == 1u)) intOK = 0;
            if (!(v == 0u || v == 0x3F800000u)) fltOK = 0;
        }
        intOK = __all_sync(0xFFFFFFFFu, intOK);
        fltOK = __all_sync(0xFFFFFFFFu, fltOK);
        if (lane == 0) g_cm_mode = intOK ? 1 : (fltOK ? 2 : 0);
    }
    // kz: warp 1 of block 64
    if (gtid >= 16416 && gtid < 16448){
        int lane = gtid - 16416;
        float v = 0.f;
        for (int d = lane; d < DIM; d += 32) v += tanhf(__ldg(&bquery[d])) * __ldg(&WW[DIM+d]);
        v = wredsum(v);
        if (lane == 0) g_kz = v;
    }
    // gier: 600 threads
    if (gtid >= 16448 && gtid < 17048){
        int idx = gtid - 16448;
        int r = idx / 300, o = idx - r*300;
        g_gier[idx] = dotw<25>(Wih1 + o*2*DIM + DIM, Er + r*DIM) + __ldg(&bih1[o]);
    }
    // qemb: all threads grid-stride
    int n = BATCH*SEQ*DIM;
    for (int i = gtid; i < n; i += 2048*256){
        int bs = i / DIM, d = i - bs*DIM;
        g_Qemb[i] = __ldg(&Eq[(size_t)question[bs]*DIM + d]);
    }
}

// ---------------- Gram matrix (unchanged) ----------------
__global__ void __launch_bounds__(256) k_gmat(){
    int b = blockIdx.y;
    int i0 = blockIdx.x * 32;
    int tid = threadIdx.x;
    __shared__ __align__(16) float sQ[32*DIM];
    const float* Qb = g_Qemb + (size_t)b*SEQ*DIM;
    for (int i = tid; i < 32*DIM; i += 256){
        int r = i / DIM, d = i - r*DIM;
        sQ[i] = Qb[(size_t)(i0 + r)*DIM + d];
    }
    __syncthreads();
    int ti = (tid >> 5) * 4;
    int tj = (tid & 31) * 4;
    float acc[4][4];
#pragma unroll
    for (int a = 0; a < 4; a++)
#pragma unroll
        for (int c = 0; c < 4; c++) acc[a][c] = 0.f;
    const float4* qi0 = (const float4*)(sQ + (ti+0)*DIM);
    const float4* qi1 = (const float4*)(sQ + (ti+1)*DIM);
    const float4* qi2 = (const float4*)(sQ + (ti+2)*DIM);
    const float4* qi3 = (const float4*)(sQ + (ti+3)*DIM);
    const float4* qj0 = (const float4*)(Qb + (size_t)(tj+0)*DIM);
    const float4* qj1 = (const float4*)(Qb + (size_t)(tj+1)*DIM);
    const float4* qj2 = (const float4*)(Qb + (size_t)(tj+2)*DIM);
    const float4* qj3 = (const float4*)(Qb + (size_t)(tj+3)*DIM);
#pragma unroll
    for (int k = 0; k < 25; k++){
        float4 A0 = qi0[k], A1 = qi1[k], A2 = qi2[k], A3 = qi3[k];
        float4 B0 = __ldg(qj0+k), B1 = __ldg(qj1+k), B2 = __ldg(qj2+k), B3 = __ldg(qj3+k);
#define GM(a,c,A,B) acc[a][c]=fmaf(A.x,B.x,acc[a][c]); acc[a][c]=fmaf(A.y,B.y,acc[a][c]); acc[a][c]=fmaf(A.z,B.z,acc[a][c]); acc[a][c]=fmaf(A.w,B.w,acc[a][c]);
        GM(0,0,A0,B0) GM(0,1,A0,B1) GM(0,2,A0,B2) GM(0,3,A0,B3)
        GM(1,0,A1,B0) GM(1,1,A1,B1) GM(1,2,A1,B2) GM(1,3,A1,B3)
        GM(2,0,A2,B0) GM(2,1,A2,B1) GM(2,2,A2,B2) GM(2,3,A2,B3)
        GM(3,0,A3,B0) GM(3,1,A3,B1) GM(3,2,A3,B2) GM(3,3,A3,B3)
#undef GM
    }
    float* Gb = g_G + (size_t)b*SEQ*SEQ;
#pragma unroll
    for (int a = 0; a < 4; a++)
#pragma unroll
        for (int c = 0; c < 4; c++)
            Gb[(size_t)(i0+ti+a)*SEQ + (tj+c)] = acc[a][c];
}

// ---------------- top-10 (unchanged) ----------------
__global__ void k_topk(){
    int wg   = blockIdx.x*(blockDim.x >> 5) + (threadIdx.x >> 5);
    int lane = threadIdx.x & 31;
    if (wg >= 116*BATCH) return;
    int t = 11 + wg / BATCH;
    int b = wg % BATCH;
    const float* Gb = g_G + (size_t)b*SEQ*SEQ;
    unsigned selm = 0;
    for (int r = 0; r < RKN; r++){
        float bv = -INFINITY; int bi = SEQ;
#pragma unroll
        for (int m = 0; m < 4; m++){
            int s = lane + 32*m;
            if (s < t && !((selm >> m) & 1u)){
                float v = __ldg(&Gb[(size_t)s*SEQ + (t+1)]);
                if (v > bv || (v == bv && s < bi)){ bv = v; bi = s; }
            }
        }
#pragma unroll
        for (int o = 16; o; o >>= 1){
            float ov = __shfl_xor_sync(0xFFFFFFFFu, bv, o);
            int   oi = __shfl_xor_sync(0xFFFFFFFFu, bi, o);
            if (ov > bv || (ov == bv && oi < bi)){ bv = ov; bi = oi; }
        }
        if ((bi & 31) == lane) selm |= 1u << (bi >> 5);
        if (lane == 0) g_top[((size_t)t*BATCH + b)*RKN + r] = bi;
    }
}

// ---------------- merged aggregate + qc: warps 0-3 agg, warps 4-7 qc ----------------
__global__ void __launch_bounds__(256) k_aggqc(
    const float* __restrict__ Eq, const float* __restrict__ Ec,
    const int* __restrict__ question, const int* __restrict__ mask,
    const int* __restrict__ qnb, const int* __restrict__ snb,
    const float* __restrict__ Wagg, const float* __restrict__ bagg,
    const float* __restrict__ Wlast, const float* __restrict__ blast,
    const int* __restrict__ concept_idx, const void* __restrict__ cmask,
    const float* __restrict__ W_key, const float* __restrict__ b_key,
    const float* __restrict__ W_W)
{
    int tb = blockIdx.x;
    int t = tb >> 7, b = tb & 127;

    __shared__ __align__(16) float sE1[4*DIM], sE2[16*DIM], sU[16*DIM], sV[16*DIM];
    __shared__ __align__(16) float sV1[4*DIM], sT4[4*DIM], sW1[4*DIM];
    __shared__ __align__(16) float vA[DIM], vB[DIM], vC[DIM];
    __shared__ int sN1[4], sN2[16], sN3[64];
    __shared__ __align__(16) float sqc[5*DIM], sQt[5*DIM];

    if (threadIdx.x < 128){
        // ================= aggregation half =================
        int tid = threadIdx.x;
        int q_t = question[b*SEQ + t];
        float* dst = g_EMB + (size_t)tb*DIM;
        if (mask[b*SEQ + t] == 0){
            for (int d = tid; d < DIM; d += 128) dst[d] = __ldg(&Eq[(size_t)q_t*DIM + d]);
        } else {
            if (tid < QNB) sN1[tid] = __ldg(&qnb[q_t*QNB + tid]);
            BAR1();
            if (tid < 16) sN2[tid] = __ldg(&snb[sN1[tid >> 2]*SNB + (tid & 3)]);
            BAR1();
            if (tid < 64) sN3[tid] = __ldg(&qnb[sN2[tid >> 2]*QNB + (tid & 3)]);
            for (int i = tid; i < 4*DIM; i += 128){
                int r = i / DIM, d = i - r*DIM;
                sE1[i] = __ldg(&Ec[(size_t)sN1[r]*DIM + d]);
            }
            BAR1();
            for (int i = tid; i < 16*DIM; i += 128){
                int k = i / DIM, d = i - k*DIM;
                float e2v = __ldg(&Eq[(size_t)sN2[k]*DIM + d]);
                float s3 = __ldg(&Ec[(size_t)sN3[4*k+0]*DIM + d]) + __ldg(&Ec[(size_t)sN3[4*k+1]*DIM + d])
                         + __ldg(&Ec[(size_t)sN3[4*k+2]*DIM + d]) + __ldg(&Ec[(size_t)sN3[4*k+3]*DIM + d]);
                sE2[i] = e2v;
                sU[i]  = e2v + 0.25f*s3;
            }
            BAR1();
            for (int task = tid; task < 4*DIM; task += 128){
                int o = task >> 2, kb = (task & 3) * 4;
                float a0=0.f,a1=0.f,a2=0.f,a3=0.f;
                dot4(Wagg + 2*DIM*DIM + o*DIM, sU+(kb+0)*DIM, sU+(kb+1)*DIM, sU+(kb+2)*DIM, sU+(kb+3)*DIM, a0,a1,a2,a3);
                float bb = __ldg(&bagg[2*DIM + o]);
                sV[(kb+0)*DIM+o] = tanhf(a0+bb);
                sV[(kb+1)*DIM+o] = tanhf(a1+bb);
                sV[(kb+2)*DIM+o] = tanhf(a2+bb);
                sV[(kb+3)*DIM+o] = tanhf(a3+bb);
            }
            for (int i = tid; i < 4*DIM; i += 128){
                int r = i / DIM, d = i - r*DIM;
                sT4[i] = sE1[i] + 0.25f*(sE2[(4*r+0)*DIM+d] + sE2[(4*r+1)*DIM+d]
                                       + sE2[(4*r+2)*DIM+d] + sE2[(4*r+3)*DIM+d]);
            }
            for (int d = tid; d < DIM; d += 128)
                vA[d] = __ldg(&Eq[(size_t)q_t*DIM + d]) + 0.25f*(sE1[d] + sE1[DIM+d] + sE1[2*DIM+d] + sE1[3*DIM+d]);
            BAR1();
            for (int o = tid; o < DIM; o += 128){
                float a0=0.f,a1=0.f,a2=0.f,a3=0.f;
                dot4(Wagg + DIM*DIM + o*DIM, sT4, sT4+DIM, sT4+2*DIM, sT4+3*DIM, a0,a1,a2,a3);
                float bb = __ldg(&bagg[DIM + o]);
                sV1[o] = tanhf(a0+bb); sV1[DIM+o] = tanhf(a1+bb);
                sV1[2*DIM+o] = tanhf(a2+bb); sV1[3*DIM+o] = tanhf(a3+bb);
                vB[o] = tanhf(dotw<25>(Wagg + o*DIM, vA) + __ldg(&bagg[o]));
            }
            BAR1();
            for (int i = tid; i < 4*DIM; i += 128){
                int r = i / DIM, d = i - r*DIM;
                sT4[i] = sV1[i] + 0.25f*(sV[(4*r+0)*DIM+d] + sV[(4*r+1)*DIM+d]
                                       + sV[(4*r+2)*DIM+d] + sV[(4*r+3)*DIM+d]);
            }
            for (int d = tid; d < DIM; d += 128)
                vA[d] = vB[d] + 0.25f*(sV1[d] + sV1[DIM+d] + sV1[2*DIM+d] + sV1[3*DIM+d]);
            BAR1();
            for (int o = tid; o < DIM; o += 128){
                float a0=0.f,a1=0.f,a2=0.f,a3=0.f;
                dot4(Wagg + DIM*DIM + o*DIM, sT4, sT4+DIM, sT4+2*DIM, sT4+3*DIM, a0,a1,a2,a3);
                float bb = __ldg(&bagg[DIM + o]);
                sW1[o] = tanhf(a0+bb); sW1[DIM+o] = tanhf(a1+bb);
                sW1[2*DIM+o] = tanhf(a2+bb); sW1[3*DIM+o] = tanhf(a3+bb);
                vC[o] = tanhf(dotw<25>(Wagg + o*DIM, vA) + __ldg(&bagg[o]));
            }
            BAR1();
            for (int d = tid; d < DIM; d += 128)
                vA[d] = vC[d] + 0.25f*(sW1[d] + sW1[DIM+d] + sW1[2*DIM+d] + sW1[3*DIM+d]);
            BAR1();
            for (int o = tid; o < DIM; o += 128)
                vB[o] = tanhf(dotw<25>(Wagg + o*DIM, vA) + __ldg(&bagg[o]));
            BAR1();
            for (int o = tid; o < DIM; o += 128)
                dst[o] = tanhf(dotw<25>(Wlast + o*DIM, vB) + __ldg(&blast[o]));
        }
    } else {
        // ================= qc half =================
        int tid = threadIdx.x - 128;
        int qn = question[b*SEQ + t + 1];
        int mode = g_cm_mode;
        for (int i = tid; i < 5*DIM; i += 128){
            int q = i / DIM, d = i - q*DIM;
            float v;
            if (q == 0){
                v = g_Qemb[((size_t)b*SEQ + t + 1)*DIM + d];
            } else {
                int fi = qn*KCN + (q - 1);
                bool mk;
                if (mode == 1)      mk = ((const int*)cmask)[fi] != 0;
                else if (mode == 2) mk = ((const float*)cmask)[fi] != 0.f;
                else                mk = ((const unsigned char*)cmask)[fi] != 0;
                int ci = __ldg(&concept_idx[fi]);
                v = mk ? __ldg(&Ec[(size_t)ci*DIM + d]) : 0.f;
            }
            sqc[i] = v;
            g_qc[((size_t)tb)*(5*DIM) + i] = v;
        }
        BAR2();
        for (int i = tid; i < 5*DIM; i += 128){
            int q = i / DIM, o = i - q*DIM;
            sQt[i] = tanhf(dotw<25>(W_key + o*DIM, sqc + q*DIM) + __ldg(&b_key[o]));
        }
        BAR2();
        int w = tid >> 5, lane = tid & 31;
        for (int q = w; q < 5; q += 4){
            float part = 0.f;
            for (int d = lane; d < DIM; d += 32) part += sQt[q*DIM + d] * __ldg(&W_W[d]);
            part = wredsum(part);
            if (lane == 0) g_qtw[((size_t)tb)*5 + q] = part;
        }
    }
}

// ---------------- gi1 (unchanged) ----------------
__global__ void __launch_bounds__(256) k_gi1(const float* __restrict__ Wih1,
                                             const int* __restrict__ response){
    int t = blockIdx.x, zb = blockIdx.y;
    int tid = threadIdx.x;
    __shared__ __align__(16) float sE[DIM*64];
    __shared__ int sRt[64];
    for (int i = tid; i < 64*DIM; i += 256){
        int bb = i / DIM, d = i - bb*DIM;
        sE[d*64 + bb] = g_EMB[((size_t)t*BATCH + zb*64 + bb)*DIM + d];
    }
    if (tid < 64) sRt[tid] = response[(zb*64 + tid)*SEQ + t];
    __syncthreads();
    for (int tt = tid; tt < 600; tt += 256){
        int ro = (tt >> 3) * 4;
        int bo = (tt & 7) * 8;
        float acc[4][8];
#pragma unroll
        for (int i = 0; i < 4; i++)
#pragma unroll
            for (int j = 0; j < 8; j++) acc[i][j] = 0.f;
        for (int k = 0; k < DIM; k++){
            float w0 = __ldg(&Wih1[(size_t)(ro+0)*2*DIM + k]);
            float w1 = __ldg(&Wih1[(size_t)(ro+1)*2*DIM + k]);
            float w2 = __ldg(&Wih1[(size_t)(ro+2)*2*DIM + k]);
            float w3 = __ldg(&Wih1[(size_t)(ro+3)*2*DIM + k]);
            const float* e = sE + k*64 + bo;
#pragma unroll
            for (int j = 0; j < 8; j++){
                float ev = e[j];
                acc[0][j] = fmaf(w0, ev, acc[0][j]);
                acc[1][j] = fmaf(w1, ev, acc[1][j]);
                acc[2][j] = fmaf(w2, ev, acc[2][j]);
                acc[3][j] = fmaf(w3, ev, acc[3][j]);
            }
        }
#pragma unroll
        for (int i = 0; i < 4; i++)
#pragma unroll
            for (int j = 0; j < 8; j++){
                int b = zb*64 + bo + j;
                int o = ro + i;
                g_GI1[((size_t)t*BATCH + b)*300 + o] = acc[i][j] + g_gier[sRt[bo+j]*300 + o];
            }
    }
}

// ---------------- pipelined scan: blocks 0-63 GRU1 (producer), 64-127 GRU2 (consumer) ----------------
__global__ void __launch_bounds__(320) k_scan2(
    const float* __restrict__ Whh1, const float* __restrict__ bhh1,
    const float* __restrict__ Wih2, const float* __restrict__ bih2,
    const float* __restrict__ Whh2, const float* __restrict__ bhh2,
    const float* __restrict__ h1i, const float* __restrict__ h2i)
{
    extern __shared__ __align__(16) float sW[];   // 30000 floats: Whh1 or Wih2
    __shared__ __align__(16) float sH[2][DIM], sX[2][DIM];
    __shared__ __align__(16) float sGa[2][300], sGb[2][300];
    __shared__ float sba[300], sbb[300];

    int tid = threadIdx.x;
    int role = blockIdx.x >> 6;          // 0 = GRU1, 1 = GRU2
    int pair = blockIdx.x & 63;
    int b0 = pair*2;

    if (role == 0){
        for (int i = tid; i < 30000; i += 320) sW[i] = Whh1[i];
        for (int i = tid; i < 300; i += 320) sba[i] = bhh1[i];
        for (int i = tid; i < DIM; i += 320){
            sH[0][i] = h1i[b0*DIM+i]; sH[1][i] = h1i[(b0+1)*DIM+i];
        }
        __syncthreads();
        for (int t = 0; t < TSTEPS; t++){
            // gh1 + gi1 load
            if (tid < 300){
                float a0 = sba[tid], a1 = sba[tid];
                dot2s(sW + tid*DIM, sH[0], sH[1], a0, a1);
                sGa[0][tid] = a0; sGa[1][tid] = a1;
            }
            for (int i = tid; i < 600; i += 320){
                int r = i / 300, o = i - r*300;
                sGb[r][o] = g_GI1[((size_t)t*BATCH + b0 + r)*300 + o];
            }
            __syncthreads();
            // h1n = GRU(gi1, gh1, h1); write smem + global
            for (int i = tid; i < 200; i += 320){
                int r = i / 100, d = i - r*100;
                float rr = sigm(sGb[r][d]       + sGa[r][d]);
                float zz = sigm(sGb[r][DIM+d]   + sGa[r][DIM+d]);
                float nn = tanhf(sGb[r][2*DIM+d] + rr*sGa[r][2*DIM+d]);
                float h1n = (1.f - zz)*nn + zz*sH[r][d];
                sH[r][d] = h1n;
                g_H1N[((size_t)t*BATCH + b0 + r)*DIM + d] = h1n;
            }
            __syncthreads();
            if (tid == 0){
                __threadfence();
                atomicExch(&g_SYNC[pair], t + 1);
            }
        }
    } else {
        for (int i = tid; i < 30000; i += 320) sW[i] = Wih2[i];
        for (int i = tid; i < 300; i += 320){ sba[i] = bhh2[i]; sbb[i] = bih2[i]; }
        for (int i = tid; i < DIM; i += 320){
            sH[0][i] = h2i[b0*DIM+i]; sH[1][i] = h2i[(b0+1)*DIM+i];
        }
        __syncthreads();
        for (int t = 0; t < TSTEPS; t++){
            // gh2 = Whh2@h2 (L1-resident global weights) — independent of h1n
            if (tid < 300){
                float a0 = sba[tid], a1 = sba[tid];
                dot2g(Whh2 + tid*DIM, sH[0], sH[1], a0, a1);
                sGa[0][tid] = a0; sGa[1][tid] = a1;
            }
            // wait for producer
            if (tid == 0){
                while (atomicAdd(&g_SYNC[pair], 0) < t + 1) __nanosleep(60);
                __threadfence();
            }
            __syncthreads();
            // load h1n
            for (int i = tid; i < 200; i += 320){
                int r = i / 100, d = i - r*100;
                sX[r][d] = g_H1N[((size_t)t*BATCH + b0 + r)*DIM + d];
            }
            __syncthreads();
            // gi2 = Wih2@h1n (smem weights)
            if (tid < 300){
                float a0 = sbb[tid], a1 = sbb[tid];
                dot2s(sW + tid*DIM, sX[0], sX[1], a0, a1);
                sGb[0][tid] = a0; sGb[1][tid] = a1;
            }
            __syncthreads();
            // g2; store; update h2 (skip at t=0)
            for (int i = tid; i < 200; i += 320){
                int r = i / 100, d = i - r*100;
                float rr = sigm(sGb[r][d]       + sGa[r][d]);
                float zz = sigm(sGb[r][DIM+d]   + sGa[r][DIM+d]);
                float nn = tanhf(sGb[r][2*DIM+d] + rr*sGa[r][2*DIM+d]);
                float g2 = (1.f - zz)*nn + zz*sH[r][d];
                g_G2ALL[((size_t)t*BATCH + b0 + r)*DIM + d] = g2;
                if (t > 0) sH[r][d] = g2;
            }
            __syncthreads();
        }
    }
}

// ---------------- ktw, 4 (t,b) per block ----------------
__global__ void __launch_bounds__(128) k_ktw(const float* __restrict__ Wquery,
                                             const float* __restrict__ bquery,
                                             const float* __restrict__ WW){
    int tb0 = blockIdx.x*4;
    int tid = threadIdx.x;
    __shared__ __align__(16) float sg2[4][DIM];
    __shared__ float sred[4][DIM];
    for (int i = tid; i < 4*DIM; i += 128){
        int j = i / DIM, d = i - j*DIM;
        sg2[j][d] = g_G2ALL[(size_t)(tb0 + j)*DIM + d];
    }
    __syncthreads();
    for (int o = tid; o < DIM; o += 128){
        float a0=0.f,a1=0.f,a2=0.f,a3=0.f;
        dot4(Wquery + o*DIM, sg2[0], sg2[1], sg2[2], sg2[3], a0,a1,a2,a3);
        float bq = __ldg(&bquery[o]);
        float wk = __ldg(&WW[DIM+o]);
        sred[0][o] = tanhf(a0+bq)*wk;
        sred[1][o] = tanhf(a1+bq)*wk;
        sred[2][o] = tanhf(a2+bq)*wk;
        sred[3][o] = tanhf(a3+bq)*wk;
    }
    __syncthreads();
    int w = tid >> 5, lane = tid & 31;
    float v = sred[w][lane] + sred[w][lane+32] + sred[w][lane+64]
            + (lane < 4 ? sred[w][lane+96] : 0.f);
    v = wredsum(v);
    if (lane == 0) g_KTW[tb0 + w] = v;
}

// ---------------- predict (128 threads) ----------------
__global__ void __launch_bounds__(128) k_predict(const float* __restrict__ bW,
                                                 float* __restrict__ out){
    int tb = blockIdx.x;
    int t = tb >> 7, b = tb & 127;
    int tid = threadIdx.x;
    __shared__ __align__(16) float sSt[11*DIM];
    __shared__ float sOg[55], sKtw[11], sQtw[5], sP[5];
    __shared__ int sSrc[11];

    if (tid < 11){
        int src = 0;
        float k;
        if (tid == 0){
            k = g_KTW[tb];
        } else {
            src = (t > RKN) ? g_top[((size_t)t*BATCH + b)*RKN + (tid-1)] : (tid-1);
            k = (src == 0) ? g_kz : g_KTW[(size_t)src*BATCH + b];
        }
        sSrc[tid] = src;
        sKtw[tid] = k;
    }
    if (tid >= 11 && tid < 16) sQtw[tid-11] = g_qtw[(size_t)tb*5 + (tid-11)];
    __syncthreads();
    for (int i = tid; i < 11*DIM; i += 128){
        int s = i / DIM, d = i - s*DIM;
        float v;
        if (s == 0) v = g_G2ALL[(size_t)tb*DIM + d];
        else {
            int src = sSrc[s];
            v = (src == 0) ? 0.f : g_G2ALL[((size_t)src*BATCH + b)*DIM + d];
        }
        sSt[i] = v;
    }
    __syncthreads();
    if (tid < 55){
        int q = tid / 11, s = tid - q*11;
        const float4* a = (const float4*)(g_qc + (size_t)tb*(5*DIM) + q*DIM);
        const float4* xx = (const float4*)(sSt + s*DIM);
        float acc = 0.f;
#pragma unroll
        for (int i = 0; i < 25; i++){
            float4 w = __ldg(a+i), u = xx[i];
            acc = fmaf(w.x,u.x,acc); acc = fmaf(w.y,u.y,acc);
            acc = fmaf(w.z,u.z,acc); acc = fmaf(w.w,u.w,acc);
        }
        sOg[tid] = acc;
    }
    __syncthreads();
    if (tid < 5){
        int q = tid;
        float bw0 = __ldg(&bW[0]);
        float qt = sQtw[q];
        float tmp[11]; float mx = -INFINITY;
#pragma unroll
        for (int s = 0; s < 11; s++){
            bool valid = (s == 0) || (t > RKN) || ((s-1) < t);
            float v = valid ? (qt + sKtw[s] + bw0) : NEGV;
            tmp[s] = v; mx = fmaxf(mx, v);
        }
        float se = 0.f, acc = 0.f;
#pragma unroll
        for (int s = 0; s < 11; s++){
            float e = expf(tmp[s] - mx);
            se += e; acc += e * sOg[q*11 + s];
        }
        sP[q] = acc / se;
    }
    __syncthreads();
    if (tid == 0){
        float p = sP[0] + sP[1] + sP[2] + sP[3] + sP[4];
        int col = (t == 0) ? 0 : (t + 1);
        out[b*SEQ + col] = p;
    }
}

// ---------------- launch ----------------
extern "C" void kernel_launch(void* const* d_in, const int* in_sizes, int n_in,
                              void* d_out, int out_size){
    const float* Eq     = (const float*)d_in[0];
    const float* Ec     = (const float*)d_in[1];
    const float* Er     = (const float*)d_in[2];
    const float* Wih1   = (const float*)d_in[3];
    const float* Whh1   = (const float*)d_in[4];
    const float* bih1   = (const float*)d_in[5];
    const float* bhh1   = (const float*)d_in[6];
    const float* Wih2   = (const float*)d_in[7];
    const float* Whh2   = (const float*)d_in[8];
    const float* bih2   = (const float*)d_in[9];
    const float* bhh2   = (const float*)d_in[10];
    const float* Wagg   = (const float*)d_in[11];
    const float* bagg   = (const float*)d_in[12];
    const float* Wlast  = (const float*)d_in[13];
    const float* blast  = (const float*)d_in[14];
    const float* Wquery = (const float*)d_in[15];
    const float* bquery = (const float*)d_in[16];
    const float* Wkey   = (const float*)d_in[17];
    const float* bkey   = (const float*)d_in[18];
    const float* WW     = (const float*)d_in[19];
    const float* bW     = (const float*)d_in[20];
    const float* h1i    = (const float*)d_in[21];
    const float* h2i    = (const float*)d_in[22];
    const int* question = (const int*)d_in[23];
    const int* response = (const int*)d_in[24];
    const int* maskp    = (const int*)d_in[25];
    const int* qnb      = (const int*)d_in[26];
    const int* snb      = (const int*)d_in[27];
    const int* cidx     = (const int*)d_in[28];
    const void* cmask   = d_in[29];
    float* out = (float*)d_out;

    cudaFuncSetAttribute(k_scan2, cudaFuncAttributeMaxDynamicSharedMemorySize, 122880);

    k_pre<<<2048, 256>>>(Eq, question, (const unsigned char*)cmask, bquery, WW,
                         Wih1, bih1, Er, out);
    k_gmat<<<dim3(4, BATCH), 256>>>();
    {
        int nwarp = 116*BATCH;
        int nb = (nwarp + 7) / 8;
        k_topk<<<nb, 256>>>();
    }
    k_aggqc<<<TSTEPS*BATCH, 256>>>(Eq, Ec, question, maskp, qnb, snb,
                                   Wagg, bagg, Wlast, blast,
                                   cidx, cmask, Wkey, bkey, WW);
    k_gi1<<<dim3(TSTEPS, 2), 256>>>(Wih1, response);
    k_scan2<<<128, 320, 120000>>>(Whh1, bhh1, Wih2, bih2, Whh2, bhh2, h1i, h2i);
    k_ktw<<<TSTEPS*BATCH/4, 128>>>(Wquery, bquery, WW);
    k_predict<<<TSTEPS*BATCH, 128>>>(bW, out);
}

// round 8
// speedup vs baseline: 7.3459x; 1.1072x over previous
#include <cuda_runtime.h>
#include <math.h>
#include <stdint.h>

#define BATCH 128
#define SEQ   128
#define DIM   100
#define QNB   4
#define SNB   4
#define KCN   4
#define RKN   10
#define TSTEPS 127
#define NEGV  -1000000000.0f

// ---------------- device scratch (no allocations) ----------------
__device__ float g_Qemb[BATCH*SEQ*DIM];
__device__ float g_G[(size_t)BATCH*SEQ*SEQ];
__device__ int   g_top[TSTEPS*BATCH*RKN];
__device__ float g_qc[(size_t)TSTEPS*BATCH*5*DIM];
__device__ float g_qtw[TSTEPS*BATCH*5];
__device__ float g_EMB[(size_t)TSTEPS*BATCH*DIM];
__device__ float g_GI1[(size_t)TSTEPS*BATCH*300];
__device__ float g_gier[2*300];
__device__ float g_H1N[(size_t)TSTEPS*BATCH*DIM];
__device__ float g_G2ALL[(size_t)TSTEPS*BATCH*DIM];
__device__ float g_KTW[TSTEPS*BATCH];
__device__ float g_kz;
__device__ int   g_cm_mode;
__device__ int   g_SYNC[64];

#define BAR1() asm volatile("bar.sync 1, 128;" ::: "memory")
#define BAR2() asm volatile("bar.sync 2, 128;" ::: "memory")

// ---------------- helpers ----------------
__device__ __forceinline__ float sigm(float x){ return 1.f/(1.f+expf(-x)); }

__device__ __forceinline__ float wredsum(float v){
#pragma unroll
    for (int o = 16; o; o >>= 1) v += __shfl_xor_sync(0xFFFFFFFFu, v, o);
    return v;
}

template<int N4>
__device__ __forceinline__ float dotw(const float* __restrict__ w, const float* x){
    const float4* w4 = reinterpret_cast<const float4*>(w);
    float acc = 0.f;
#pragma unroll
    for (int i = 0; i < N4; i++){
        float4 wv = __ldg(w4+i);
        acc = fmaf(wv.x, x[4*i+0], acc);
        acc = fmaf(wv.y, x[4*i+1], acc);
        acc = fmaf(wv.z, x[4*i+2], acc);
        acc = fmaf(wv.w, x[4*i+3], acc);
    }
    return acc;
}

__device__ __forceinline__ void dot2s(const float* w, const float* x0, const float* x1,
                                      float& a0, float& a1){
    const float4* w4 = (const float4*)w;
    const float4* p0 = (const float4*)x0;
    const float4* p1 = (const float4*)x1;
#pragma unroll
    for (int i = 0; i < 25; i++){
        float4 wv = w4[i];
        float4 u = p0[i], v = p1[i];
        a0 = fmaf(wv.x,u.x,a0); a0 = fmaf(wv.y,u.y,a0); a0 = fmaf(wv.z,u.z,a0); a0 = fmaf(wv.w,u.w,a0);
        a1 = fmaf(wv.x,v.x,a1); a1 = fmaf(wv.y,v.y,a1); a1 = fmaf(wv.z,v.z,a1); a1 = fmaf(wv.w,v.w,a1);
    }
}

__device__ __forceinline__ void dot2g(const float* __restrict__ w, const float* x0, const float* x1,
                                      float& a0, float& a1){
    const float4* w4 = (const float4*)w;
    const float4* p0 = (const float4*)x0;
    const float4* p1 = (const float4*)x1;
#pragma unroll
    for (int i = 0; i < 25; i++){
        float4 wv = __ldg(w4+i);
        float4 u = p0[i], v = p1[i];
        a0 = fmaf(wv.x,u.x,a0); a0 = fmaf(wv.y,u.y,a0); a0 = fmaf(wv.z,u.z,a0); a0 = fmaf(wv.w,u.w,a0);
        a1 = fmaf(wv.x,v.x,a1); a1 = fmaf(wv.y,v.y,a1); a1 = fmaf(wv.z,v.z,a1); a1 = fmaf(wv.w,v.w,a1);
    }
}

__device__ __forceinline__ void dot4(const float* __restrict__ w,
        const float* x0, const float* x1, const float* x2, const float* x3,
        float& a0, float& a1, float& a2, float& a3){
    const float4* w4 = (const float4*)w;
    const float4* p0 = (const float4*)x0;
    const float4* p1 = (const float4*)x1;
    const float4* p2 = (const float4*)x2;
    const float4* p3 = (const float4*)x3;
#pragma unroll
    for (int i = 0; i < 25; i++){
        float4 wv = __ldg(w4+i);
        float4 u0 = p0[i], u1 = p1[i], u2 = p2[i], u3 = p3[i];
        a0 = fmaf(wv.x,u0.x,a0); a0 = fmaf(wv.y,u0.y,a0); a0 = fmaf(wv.z,u0.z,a0); a0 = fmaf(wv.w,u0.w,a0);
        a1 = fmaf(wv.x,u1.x,a1); a1 = fmaf(wv.y,u1.y,a1); a1 = fmaf(wv.z,u1.z,a1); a1 = fmaf(wv.w,u1.w,a1);
        a2 = fmaf(wv.x,u2.x,a2); a2 = fmaf(wv.y,u2.y,a2); a2 = fmaf(wv.z,u2.z,a2); a2 = fmaf(wv.w,u2.w,a2);
        a3 = fmaf(wv.x,u3.x,a3); a3 = fmaf(wv.y,u3.y,a3); a3 = fmaf(wv.z,u3.z,a3); a3 = fmaf(wv.w,u3.w,a3);
    }
}

#define FMA4(acc,Wv,Xv) { acc = fmaf(Wv.x,Xv.x,acc); acc = fmaf(Wv.y,Xv.y,acc); \
                          acc = fmaf(Wv.z,Xv.z,acc); acc = fmaf(Wv.w,Xv.w,acc); }

// ---------------- fused setup ----------------
__global__ void __launch_bounds__(256) k_pre(
    const float* __restrict__ Eq, const int* __restrict__ question,
    const unsigned char* __restrict__ cm,
    const float* __restrict__ bquery, const float* __restrict__ WW,
    const float* __restrict__ Wih1, const float* __restrict__ bih1,
    const float* __restrict__ Er, float* __restrict__ out)
{
    int gtid = blockIdx.x*256 + threadIdx.x;
    if (gtid < BATCH*SEQ) out[gtid] = 0.f;
    if (gtid < 64) g_SYNC[gtid] = 0;
    if (gtid >= 16384 && gtid < 16416){
        int lane = gtid - 16384;
        int intOK = 1, fltOK = 1;
        for (int g = lane; g < 1000; g += 32){
            uint32_t v = 0;
            v |= (uint32_t)cm[4*g+0];
            v |= (uint32_t)cm[4*g+1] << 8;
            v |= (uint32_t)cm[4*g+2] << 16;
            v |= (uint32_t)cm[4*g+3] << 24;
            if (!(v == 0u || v == 1u)) intOK = 0;
            if (!(v == 0u || v == 0x3F800000u)) fltOK = 0;
        }
        intOK = __all_sync(0xFFFFFFFFu, intOK);
        fltOK = __all_sync(0xFFFFFFFFu, fltOK);
        if (lane == 0) g_cm_mode = intOK ? 1 : (fltOK ? 2 : 0);
    }
    if (gtid >= 16416 && gtid < 16448){
        int lane = gtid - 16416;
        float v = 0.f;
        for (int d = lane; d < DIM; d += 32) v += tanhf(__ldg(&bquery[d])) * __ldg(&WW[DIM+d]);
        v = wredsum(v);
        if (lane == 0) g_kz = v;
    }
    if (gtid >= 16448 && gtid < 17048){
        int idx = gtid - 16448;
        int r = idx / 300, o = idx - r*300;
        g_gier[idx] = dotw<25>(Wih1 + o*2*DIM + DIM, Er + r*DIM) + __ldg(&bih1[o]);
    }
    int n = BATCH*SEQ*DIM;
    for (int i = gtid; i < n; i += 2048*256){
        int bs = i / DIM, d = i - bs*DIM;
        g_Qemb[i] = __ldg(&Eq[(size_t)question[bs]*DIM + d]);
    }
}

// ---------------- Gram matrix ----------------
__global__ void __launch_bounds__(256) k_gmat(){
    int b = blockIdx.y;
    int i0 = blockIdx.x * 32;
    int tid = threadIdx.x;
    __shared__ __align__(16) float sQ[32*DIM];
    const float* Qb = g_Qemb + (size_t)b*SEQ*DIM;
    for (int i = tid; i < 32*DIM; i += 256){
        int r = i / DIM, d = i - r*DIM;
        sQ[i] = Qb[(size_t)(i0 + r)*DIM + d];
    }
    __syncthreads();
    int ti = (tid >> 5) * 4;
    int tj = (tid & 31) * 4;
    float acc[4][4];
#pragma unroll
    for (int a = 0; a < 4; a++)
#pragma unroll
        for (int c = 0; c < 4; c++) acc[a][c] = 0.f;
    const float4* qi0 = (const float4*)(sQ + (ti+0)*DIM);
    const float4* qi1 = (const float4*)(sQ + (ti+1)*DIM);
    const float4* qi2 = (const float4*)(sQ + (ti+2)*DIM);
    const float4* qi3 = (const float4*)(sQ + (ti+3)*DIM);
    const float4* qj0 = (const float4*)(Qb + (size_t)(tj+0)*DIM);
    const float4* qj1 = (const float4*)(Qb + (size_t)(tj+1)*DIM);
    const float4* qj2 = (const float4*)(Qb + (size_t)(tj+2)*DIM);
    const float4* qj3 = (const float4*)(Qb + (size_t)(tj+3)*DIM);
#pragma unroll
    for (int k = 0; k < 25; k++){
        float4 A0 = qi0[k], A1 = qi1[k], A2 = qi2[k], A3 = qi3[k];
        float4 B0 = __ldg(qj0+k), B1 = __ldg(qj1+k), B2 = __ldg(qj2+k), B3 = __ldg(qj3+k);
        FMA4(acc[0][0],A0,B0) FMA4(acc[0][1],A0,B1) FMA4(acc[0][2],A0,B2) FMA4(acc[0][3],A0,B3)
        FMA4(acc[1][0],A1,B0) FMA4(acc[1][1],A1,B1) FMA4(acc[1][2],A1,B2) FMA4(acc[1][3],A1,B3)
        FMA4(acc[2][0],A2,B0) FMA4(acc[2][1],A2,B1) FMA4(acc[2][2],A2,B2) FMA4(acc[2][3],A2,B3)
        FMA4(acc[3][0],A3,B0) FMA4(acc[3][1],A3,B1) FMA4(acc[3][2],A3,B2) FMA4(acc[3][3],A3,B3)
    }
    float* Gb = g_G + (size_t)b*SEQ*SEQ;
#pragma unroll
    for (int a = 0; a < 4; a++)
#pragma unroll
        for (int c = 0; c < 4; c++)
            Gb[(size_t)(i0+ti+a)*SEQ + (tj+c)] = acc[a][c];
}

// ---------------- top-10 ----------------
__global__ void k_topk(){
    int wg   = blockIdx.x*(blockDim.x >> 5) + (threadIdx.x >> 5);
    int lane = threadIdx.x & 31;
    if (wg >= 116*BATCH) return;
    int t = 11 + wg / BATCH;
    int b = wg % BATCH;
    const float* Gb = g_G + (size_t)b*SEQ*SEQ;
    unsigned selm = 0;
    for (int r = 0; r < RKN; r++){
        float bv = -INFINITY; int bi = SEQ;
#pragma unroll
        for (int m = 0; m < 4; m++){
            int s = lane + 32*m;
            if (s < t && !((selm >> m) & 1u)){
                float v = __ldg(&Gb[(size_t)s*SEQ + (t+1)]);
                if (v > bv || (v == bv && s < bi)){ bv = v; bi = s; }
            }
        }
#pragma unroll
        for (int o = 16; o; o >>= 1){
            float ov = __shfl_xor_sync(0xFFFFFFFFu, bv, o);
            int   oi = __shfl_xor_sync(0xFFFFFFFFu, bi, o);
            if (ov > bv || (ov == bv && oi < bi)){ bv = ov; bi = oi; }
        }
        if ((bi & 31) == lane) selm |= 1u << (bi >> 5);
        if (lane == 0) g_top[((size_t)t*BATCH + b)*RKN + r] = bi;
    }
}

// ---------------- merged aggregate + qc (deep register tiling) ----------------
__global__ void __launch_bounds__(256) k_aggqc(
    const float* __restrict__ Eq, const float* __restrict__ Ec,
    const int* __restrict__ question, const int* __restrict__ mask,
    const int* __restrict__ qnb, const int* __restrict__ snb,
    const float* __restrict__ Wagg, const float* __restrict__ bagg,
    const float* __restrict__ Wlast, const float* __restrict__ blast,
    const int* __restrict__ concept_idx, const void* __restrict__ cmask,
    const float* __restrict__ W_key, const float* __restrict__ b_key,
    const float* __restrict__ W_W)
{
    int tb = blockIdx.x;
    int t = tb >> 7, b = tb & 127;

    __shared__ __align__(16) float sE1[4*DIM], sE2[16*DIM], sU[16*DIM], sV[16*DIM];
    __shared__ __align__(16) float sV1[4*DIM], sT4[4*DIM], sW1[4*DIM];
    __shared__ __align__(16) float vA[DIM], vB[DIM], vC[DIM];
    __shared__ int sN1[4], sN2[16], sN3[64];
    __shared__ __align__(16) float sqc[5*DIM], sQt[5*DIM];

    if (threadIdx.x < 128){
        // ================= aggregation half =================
        int tid = threadIdx.x;
        int q_t = question[b*SEQ + t];
        float* dst = g_EMB + (size_t)tb*DIM;
        if (mask[b*SEQ + t] == 0){
            for (int d = tid; d < DIM; d += 128) dst[d] = __ldg(&Eq[(size_t)q_t*DIM + d]);
        } else {
            if (tid < QNB) sN1[tid] = __ldg(&qnb[q_t*QNB + tid]);
            BAR1();
            if (tid < 16) sN2[tid] = __ldg(&snb[sN1[tid >> 2]*SNB + (tid & 3)]);
            BAR1();
            if (tid < 64) sN3[tid] = __ldg(&qnb[sN2[tid >> 2]*QNB + (tid & 3)]);
            for (int i = tid; i < 4*DIM; i += 128){
                int r = i / DIM, d = i - r*DIM;
                sE1[i] = __ldg(&Ec[(size_t)sN1[r]*DIM + d]);
            }
            BAR1();
            for (int i = tid; i < 16*DIM; i += 128){
                int k = i / DIM, d = i - k*DIM;
                float e2v = __ldg(&Eq[(size_t)sN2[k]*DIM + d]);
                float s3 = __ldg(&Ec[(size_t)sN3[4*k+0]*DIM + d]) + __ldg(&Ec[(size_t)sN3[4*k+1]*DIM + d])
                         + __ldg(&Ec[(size_t)sN3[4*k+2]*DIM + d]) + __ldg(&Ec[(size_t)sN3[4*k+3]*DIM + d]);
                sE2[i] = e2v;
                sU[i]  = e2v + 0.25f*s3;
            }
            BAR1();
            // ---- stage i=0: sV[k][o] = tanh(Wagg2 @ sU[k] + b2), 4o x 4k register tiles ----
            for (int task = tid; task < 100; task += 128){
                int og = task % 25, kg = task / 25;
                int o0 = og*4, k0 = kg*4;
                float acc[4][4];
#pragma unroll
                for (int a = 0; a < 4; a++)
#pragma unroll
                    for (int c = 0; c < 4; c++) acc[a][c] = 0.f;
                const float4* w0 = (const float4*)(Wagg + 2*DIM*DIM + (o0+0)*DIM);
                const float4* w1 = (const float4*)(Wagg + 2*DIM*DIM + (o0+1)*DIM);
                const float4* w2 = (const float4*)(Wagg + 2*DIM*DIM + (o0+2)*DIM);
                const float4* w3 = (const float4*)(Wagg + 2*DIM*DIM + (o0+3)*DIM);
                const float4* x0 = (const float4*)(sU + (k0+0)*DIM);
                const float4* x1 = (const float4*)(sU + (k0+1)*DIM);
                const float4* x2 = (const float4*)(sU + (k0+2)*DIM);
                const float4* x3 = (const float4*)(sU + (k0+3)*DIM);
#pragma unroll
                for (int i = 0; i < 25; i++){
                    float4 W0 = __ldg(w0+i), W1 = __ldg(w1+i), W2 = __ldg(w2+i), W3 = __ldg(w3+i);
                    float4 X0 = x0[i], X1 = x1[i], X2 = x2[i], X3 = x3[i];
                    FMA4(acc[0][0],W0,X0) FMA4(acc[0][1],W0,X1) FMA4(acc[0][2],W0,X2) FMA4(acc[0][3],W0,X3)
                    FMA4(acc[1][0],W1,X0) FMA4(acc[1][1],W1,X1) FMA4(acc[1][2],W1,X2) FMA4(acc[1][3],W1,X3)
                    FMA4(acc[2][0],W2,X0) FMA4(acc[2][1],W2,X1) FMA4(acc[2][2],W2,X2) FMA4(acc[2][3],W2,X3)
                    FMA4(acc[3][0],W3,X0) FMA4(acc[3][1],W3,X1) FMA4(acc[3][2],W3,X2) FMA4(acc[3][3],W3,X3)
                }
#pragma unroll
                for (int a = 0; a < 4; a++){
                    float bb = __ldg(&bagg[2*DIM + o0 + a]);
#pragma unroll
                    for (int c = 0; c < 4; c++)
                        sV[(k0+c)*DIM + (o0+a)] = tanhf(acc[a][c] + bb);
                }
            }
            for (int i = tid; i < 4*DIM; i += 128){
                int r = i / DIM, d = i - r*DIM;
                sT4[i] = sE1[i] + 0.25f*(sE2[(4*r+0)*DIM+d] + sE2[(4*r+1)*DIM+d]
                                       + sE2[(4*r+2)*DIM+d] + sE2[(4*r+3)*DIM+d]);
            }
            for (int d = tid; d < DIM; d += 128)
                vA[d] = __ldg(&Eq[(size_t)q_t*DIM + d]) + 0.25f*(sE1[d] + sE1[DIM+d] + sE1[2*DIM+d] + sE1[3*DIM+d]);
            BAR1();
            // ---- sV1 = tanh(Wagg1 @ sT4) (2o x 4r), vB = tanh(Wagg0 @ vA) (2o) ----
            for (int task = tid; task < 100; task += 128){
                if (task < 50){
                    int o0 = task*2;
                    float acc[2][4];
#pragma unroll
                    for (int a = 0; a < 2; a++)
#pragma unroll
                        for (int c = 0; c < 4; c++) acc[a][c] = 0.f;
                    const float4* w0 = (const float4*)(Wagg + DIM*DIM + (o0+0)*DIM);
                    const float4* w1 = (const float4*)(Wagg + DIM*DIM + (o0+1)*DIM);
                    const float4* x0 = (const float4*)(sT4 + 0*DIM);
                    const float4* x1 = (const float4*)(sT4 + 1*DIM);
                    const float4* x2 = (const float4*)(sT4 + 2*DIM);
                    const float4* x3 = (const float4*)(sT4 + 3*DIM);
#pragma unroll
                    for (int i = 0; i < 25; i++){
                        float4 W0 = __ldg(w0+i), W1 = __ldg(w1+i);
                        float4 X0 = x0[i], X1 = x1[i], X2 = x2[i], X3 = x3[i];
                        FMA4(acc[0][0],W0,X0) FMA4(acc[0][1],W0,X1) FMA4(acc[0][2],W0,X2) FMA4(acc[0][3],W0,X3)
                        FMA4(acc[1][0],W1,X0) FMA4(acc[1][1],W1,X1) FMA4(acc[1][2],W1,X2) FMA4(acc[1][3],W1,X3)
                    }
#pragma unroll
                    for (int a = 0; a < 2; a++){
                        float bb = __ldg(&bagg[DIM + o0 + a]);
#pragma unroll
                        for (int c = 0; c < 4; c++)
                            sV1[c*DIM + (o0+a)] = tanhf(acc[a][c] + bb);
                    }
                } else {
                    int o0 = (task - 50)*2;
                    float a0 = 0.f, a1 = 0.f;
                    dot2g(Wagg + o0*DIM, vA, vA, a0, a0);   // dummy-safe? no — use explicit:
                    a0 = dotw<25>(Wagg + (o0+0)*DIM, vA);
                    a1 = dotw<25>(Wagg + (o0+1)*DIM, vA);
                    vB[o0+0] = tanhf(a0 + __ldg(&bagg[o0+0]));
                    vB[o0+1] = tanhf(a1 + __ldg(&bagg[o0+1]));
                }
            }
            BAR1();
            // ---- stage i=1 averaging ----
            for (int i = tid; i < 4*DIM; i += 128){
                int r = i / DIM, d = i - r*DIM;
                sT4[i] = sV1[i] + 0.25f*(sV[(4*r+0)*DIM+d] + sV[(4*r+1)*DIM+d]
                                       + sV[(4*r+2)*DIM+d] + sV[(4*r+3)*DIM+d]);
            }
            for (int d = tid; d < DIM; d += 128)
                vA[d] = vB[d] + 0.25f*(sV1[d] + sV1[DIM+d] + sV1[2*DIM+d] + sV1[3*DIM+d]);
            BAR1();
            // ---- sW1 = tanh(Wagg1 @ sT4) (2o x 4r), vC = tanh(Wagg0 @ vA) (2o) ----
            for (int task = tid; task < 100; task += 128){
                if (task < 50){
                    int o0 = task*2;
                    float acc[2][4];
#pragma unroll
                    for (int a = 0; a < 2; a++)
#pragma unroll
                        for (int c = 0; c < 4; c++) acc[a][c] = 0.f;
                    const float4* w0 = (const float4*)(Wagg + DIM*DIM + (o0+0)*DIM);
                    const float4* w1 = (const float4*)(Wagg + DIM*DIM + (o0+1)*DIM);
                    const float4* x0 = (const float4*)(sT4 + 0*DIM);
                    const float4* x1 = (const float4*)(sT4 + 1*DIM);
                    const float4* x2 = (const float4*)(sT4 + 2*DIM);
                    const float4* x3 = (const float4*)(sT4 + 3*DIM);
#pragma unroll
                    for (int i = 0; i < 25; i++){
                        float4 W0 = __ldg(w0+i), W1 = __ldg(w1+i);
                        float4 X0 = x0[i], X1 = x1[i], X2 = x2[i], X3 = x3[i];
                        FMA4(acc[0][0],W0,X0) FMA4(acc[0][1],W0,X1) FMA4(acc[0][2],W0,X2) FMA4(acc[0][3],W0,X3)
                        FMA4(acc[1][0],W1,X0) FMA4(acc[1][1],W1,X1) FMA4(acc[1][2],W1,X2) FMA4(acc[1][3],W1,X3)
                    }
#pragma unroll
                    for (int a = 0; a < 2; a++){
                        float bb = __ldg(&bagg[DIM + o0 + a]);
#pragma unroll
                        for (int c = 0; c < 4; c++)
                            sW1[c*DIM + (o0+a)] = tanhf(acc[a][c] + bb);
                    }
                } else {
                    int o0 = (task - 50)*2;
                    float a0 = dotw<25>(Wagg + (o0+0)*DIM, vA);
                    float a1 = dotw<25>(Wagg + (o0+1)*DIM, vA);
                    vC[o0+0] = tanhf(a0 + __ldg(&bagg[o0+0]));
                    vC[o0+1] = tanhf(a1 + __ldg(&bagg[o0+1]));
                }
            }
            BAR1();
            // ---- stage i=2 ----
            for (int d = tid; d < DIM; d += 128)
                vA[d] = vC[d] + 0.25f*(sW1[d] + sW1[DIM+d] + sW1[2*DIM+d] + sW1[3*DIM+d]);
            BAR1();
            for (int task = tid; task < 50; task += 128){
                int o0 = task*2;
                float a0 = dotw<25>(Wagg + (o0+0)*DIM, vA);
                float a1 = dotw<25>(Wagg + (o0+1)*DIM, vA);
                vB[o0+0] = tanhf(a0 + __ldg(&bagg[o0+0]));
                vB[o0+1] = tanhf(a1 + __ldg(&bagg[o0+1]));
            }
            BAR1();
            for (int task = tid; task < 50; task += 128){
                int o0 = task*2;
                float a0 = dotw<25>(Wlast + (o0+0)*DIM, vB);
                float a1 = dotw<25>(Wlast + (o0+1)*DIM, vB);
                dst[o0+0] = tanhf(a0 + __ldg(&blast[o0+0]));
                dst[o0+1] = tanhf(a1 + __ldg(&blast[o0+1]));
            }
        }
    } else {
        // ================= qc half =================
        int tid = threadIdx.x - 128;
        int qn = question[b*SEQ + t + 1];
        int mode = g_cm_mode;
        for (int i = tid; i < 5*DIM; i += 128){
            int q = i / DIM, d = i - q*DIM;
            float v;
            if (q == 0){
                v = g_Qemb[((size_t)b*SEQ + t + 1)*DIM + d];
            } else {
                int fi = qn*KCN + (q - 1);
                bool mk;
                if (mode == 1)      mk = ((const int*)cmask)[fi] != 0;
                else if (mode == 2) mk = ((const float*)cmask)[fi] != 0.f;
                else                mk = ((const unsigned char*)cmask)[fi] != 0;
                int ci = __ldg(&concept_idx[fi]);
                v = mk ? __ldg(&Ec[(size_t)ci*DIM + d]) : 0.f;
            }
            sqc[i] = v;
            g_qc[((size_t)tb)*(5*DIM) + i] = v;
        }
        BAR2();
        // ---- sQt = tanh(W_key @ sqc + b_key), 2o x 5q tiles ----
        for (int task = tid; task < 50; task += 128){
            int o0 = task*2;
            float acc[2][5];
#pragma unroll
            for (int a = 0; a < 2; a++)
#pragma unroll
                for (int c = 0; c < 5; c++) acc[a][c] = 0.f;
            const float4* w0 = (const float4*)(W_key + (o0+0)*DIM);
            const float4* w1 = (const float4*)(W_key + (o0+1)*DIM);
            const float4* x0 = (const float4*)(sqc + 0*DIM);
            const float4* x1 = (const float4*)(sqc + 1*DIM);
            const float4* x2 = (const float4*)(sqc + 2*DIM);
            const float4* x3 = (const float4*)(sqc + 3*DIM);
            const float4* x4 = (const float4*)(sqc + 4*DIM);
#pragma unroll
            for (int i = 0; i < 25; i++){
                float4 W0 = __ldg(w0+i), W1 = __ldg(w1+i);
                float4 X0 = x0[i], X1 = x1[i], X2 = x2[i], X3 = x3[i], X4 = x4[i];
                FMA4(acc[0][0],W0,X0) FMA4(acc[0][1],W0,X1) FMA4(acc[0][2],W0,X2) FMA4(acc[0][3],W0,X3) FMA4(acc[0][4],W0,X4)
                FMA4(acc[1][0],W1,X0) FMA4(acc[1][1],W1,X1) FMA4(acc[1][2],W1,X2) FMA4(acc[1][3],W1,X3) FMA4(acc[1][4],W1,X4)
            }
#pragma unroll
            for (int a = 0; a < 2; a++){
                float bb = __ldg(&b_key[o0+a]);
#pragma unroll
                for (int c = 0; c < 5; c++)
                    sQt[c*DIM + (o0+a)] = tanhf(acc[a][c] + bb);
            }
        }
        BAR2();
        int w = tid >> 5, lane = tid & 31;
        for (int q = w; q < 5; q += 4){
            float part = 0.f;
            for (int d = lane; d < DIM; d += 32) part += sQt[q*DIM + d] * __ldg(&W_W[d]);
            part = wredsum(part);
            if (lane == 0) g_qtw[((size_t)tb)*5 + q] = part;
        }
    }
}

// ---------------- gi1 ----------------
__global__ void __launch_bounds__(256) k_gi1(const float* __restrict__ Wih1,
                                             const int* __restrict__ response){
    int t = blockIdx.x, zb = blockIdx.y;
    int tid = threadIdx.x;
    __shared__ __align__(16) float sE[DIM*64];
    __shared__ int sRt[64];
    for (int i = tid; i < 64*DIM; i += 256){
        int bb = i / DIM, d = i - bb*DIM;
        sE[d*64 + bb] = g_EMB[((size_t)t*BATCH + zb*64 + bb)*DIM + d];
    }
    if (tid < 64) sRt[tid] = response[(zb*64 + tid)*SEQ + t];
    __syncthreads();
    for (int tt = tid; tt < 600; tt += 256){
        int ro = (tt >> 3) * 4;
        int bo = (tt & 7) * 8;
        float acc[4][8];
#pragma unroll
        for (int i = 0; i < 4; i++)
#pragma unroll
            for (int j = 0; j < 8; j++) acc[i][j] = 0.f;
        for (int k = 0; k < DIM; k++){
            float w0 = __ldg(&Wih1[(size_t)(ro+0)*2*DIM + k]);
            float w1 = __ldg(&Wih1[(size_t)(ro+1)*2*DIM + k]);
            float w2 = __ldg(&Wih1[(size_t)(ro+2)*2*DIM + k]);
            float w3 = __ldg(&Wih1[(size_t)(ro+3)*2*DIM + k]);
            const float* e = sE + k*64 + bo;
#pragma unroll
            for (int j = 0; j < 8; j++){
                float ev = e[j];
                acc[0][j] = fmaf(w0, ev, acc[0][j]);
                acc[1][j] = fmaf(w1, ev, acc[1][j]);
                acc[2][j] = fmaf(w2, ev, acc[2][j]);
                acc[3][j] = fmaf(w3, ev, acc[3][j]);
            }
        }
#pragma unroll
        for (int i = 0; i < 4; i++)
#pragma unroll
            for (int j = 0; j < 8; j++){
                int b = zb*64 + bo + j;
                int o = ro + i;
                g_GI1[((size_t)t*BATCH + b)*300 + o] = acc[i][j] + g_gier[sRt[bo+j]*300 + o];
            }
    }
}

// ---------------- pipelined scan ----------------
__global__ void __launch_bounds__(320) k_scan2(
    const float* __restrict__ Whh1, const float* __restrict__ bhh1,
    const float* __restrict__ Wih2, const float* __restrict__ bih2,
    const float* __restrict__ Whh2, const float* __restrict__ bhh2,
    const float* __restrict__ h1i, const float* __restrict__ h2i)
{
    extern __shared__ __align__(16) float sW[];
    __shared__ __align__(16) float sH[2][DIM], sX[2][DIM];
    __shared__ __align__(16) float sGa[2][300], sGb[2][300];
    __shared__ float sba[300], sbb[300];

    int tid = threadIdx.x;
    int role = blockIdx.x >> 6;
    int pair = blockIdx.x & 63;
    int b0 = pair*2;

    if (role == 0){
        for (int i = tid; i < 30000; i += 320) sW[i] = Whh1[i];
        for (int i = tid; i < 300; i += 320) sba[i] = bhh1[i];
        for (int i = tid; i < DIM; i += 320){
            sH[0][i] = h1i[b0*DIM+i]; sH[1][i] = h1i[(b0+1)*DIM+i];
        }
        __syncthreads();
        for (int t = 0; t < TSTEPS; t++){
            if (tid < 300){
                float a0 = sba[tid], a1 = sba[tid];
                dot2s(sW + tid*DIM, sH[0], sH[1], a0, a1);
                sGa[0][tid] = a0; sGa[1][tid] = a1;
            }
            for (int i = tid; i < 600; i += 320){
                int r = i / 300, o = i - r*300;
                sGb[r][o] = g_GI1[((size_t)t*BATCH + b0 + r)*300 + o];
            }
            __syncthreads();
            for (int i = tid; i < 200; i += 320){
                int r = i / 100, d = i - r*100;
                float rr = sigm(sGb[r][d]       + sGa[r][d]);
                float zz = sigm(sGb[r][DIM+d]   + sGa[r][DIM+d]);
                float nn = tanhf(sGb[r][2*DIM+d] + rr*sGa[r][2*DIM+d]);
                float h1n = (1.f - zz)*nn + zz*sH[r][d];
                sH[r][d] = h1n;
                g_H1N[((size_t)t*BATCH + b0 + r)*DIM + d] = h1n;
            }
            __syncthreads();
            if (tid == 0){
                __threadfence();
                atomicExch(&g_SYNC[pair], t + 1);
            }
        }
    } else {
        for (int i = tid; i < 30000; i += 320) sW[i] = Wih2[i];
        for (int i = tid; i < 300; i += 320){ sba[i] = bhh2[i]; sbb[i] = bih2[i]; }
        for (int i = tid; i < DIM; i += 320){
            sH[0][i] = h2i[b0*DIM+i]; sH[1][i] = h2i[(b0+1)*DIM+i];
        }
        __syncthreads();
        for (int t = 0; t < TSTEPS; t++){
            if (tid < 300){
                float a0 = sba[tid], a1 = sba[tid];
                dot2g(Whh2 + tid*DIM, sH[0], sH[1], a0, a1);
                sGa[0][tid] = a0; sGa[1][tid] = a1;
            }
            if (tid == 0){
                while (atomicAdd(&g_SYNC[pair], 0) < t + 1) __nanosleep(60);
                __threadfence();
            }
            __syncthreads();
            for (int i = tid; i < 200; i += 320){
                int r = i / 100, d = i - r*100;
                sX[r][d] = g_H1N[((size_t)t*BATCH + b0 + r)*DIM + d];
            }
            __syncthreads();
            if (tid < 300){
                float a0 = sbb[tid], a1 = sbb[tid];
                dot2s(sW + tid*DIM, sX[0], sX[1], a0, a1);
                sGb[0][tid] = a0; sGb[1][tid] = a1;
            }
            __syncthreads();
            for (int i = tid; i < 200; i += 320){
                int r = i / 100, d = i - r*100;
                float rr = sigm(sGb[r][d]       + sGa[r][d]);
                float zz = sigm(sGb[r][DIM+d]   + sGa[r][DIM+d]);
                float nn = tanhf(sGb[r][2*DIM+d] + rr*sGa[r][2*DIM+d]);
                float g2 = (1.f - zz)*nn + zz*sH[r][d];
                g_G2ALL[((size_t)t*BATCH + b0 + r)*DIM + d] = g2;
                if (t > 0) sH[r][d] = g2;
            }
            __syncthreads();
        }
    }
}

// ---------------- ktw, 4 per block ----------------
__global__ void __launch_bounds__(128) k_ktw(const float* __restrict__ Wquery,
                                             const float* __restrict__ bquery,
                                             const float* __restrict__ WW){
    int tb0 = blockIdx.x*4;
    int tid = threadIdx.x;
    __shared__ __align__(16) float sg2[4][DIM];
    __shared__ float sred[4][DIM];
    for (int i = tid; i < 4*DIM; i += 128){
        int j = i / DIM, d = i - j*DIM;
        sg2[j][d] = g_G2ALL[(size_t)(tb0 + j)*DIM + d];
    }
    __syncthreads();
    for (int o = tid; o < DIM; o += 128){
        float a0=0.f,a1=0.f,a2=0.f,a3=0.f;
        dot4(Wquery + o*DIM, sg2[0], sg2[1], sg2[2], sg2[3], a0,a1,a2,a3);
        float bq = __ldg(&bquery[o]);
        float wk = __ldg(&WW[DIM+o]);
        sred[0][o] = tanhf(a0+bq)*wk;
        sred[1][o] = tanhf(a1+bq)*wk;
        sred[2][o] = tanhf(a2+bq)*wk;
        sred[3][o] = tanhf(a3+bq)*wk;
    }
    __syncthreads();
    int w = tid >> 5, lane = tid & 31;
    float v = sred[w][lane] + sred[w][lane+32] + sred[w][lane+64]
            + (lane < 4 ? sred[w][lane+96] : 0.f);
    v = wredsum(v);
    if (lane == 0) g_KTW[tb0 + w] = v;
}

// ---------------- predict ----------------
__global__ void __launch_bounds__(128) k_predict(const float* __restrict__ bW,
                                                 float* __restrict__ out){
    int tb = blockIdx.x;
    int t = tb >> 7, b = tb & 127;
    int tid = threadIdx.x;
    __shared__ __align__(16) float sSt[11*DIM];
    __shared__ float sOg[55], sKtw[11], sQtw[5], sP[5];
    __shared__ int sSrc[11];

    if (tid < 11){
        int src = 0;
        float k;
        if (tid == 0){
            k = g_KTW[tb];
        } else {
            src = (t > RKN) ? g_top[((size_t)t*BATCH + b)*RKN + (tid-1)] : (tid-1);
            k = (src == 0) ? g_kz : g_KTW[(size_t)src*BATCH + b];
        }
        sSrc[tid] = src;
        sKtw[tid] = k;
    }
    if (tid >= 11 && tid < 16) sQtw[tid-11] = g_qtw[(size_t)tb*5 + (tid-11)];
    __syncthreads();
    for (int i = tid; i < 11*DIM; i += 128){
        int s = i / DIM, d = i - s*DIM;
        float v;
        if (s == 0) v = g_G2ALL[(size_t)tb*DIM + d];
        else {
            int src = sSrc[s];
            v = (src == 0) ? 0.f : g_G2ALL[((size_t)src*BATCH + b)*DIM + d];
        }
        sSt[i] = v;
    }
    __syncthreads();
    if (tid < 55){
        int q = tid / 11, s = tid - q*11;
        const float4* a = (const float4*)(g_qc + (size_t)tb*(5*DIM) + q*DIM);
        const float4* xx = (const float4*)(sSt + s*DIM);
        float acc = 0.f;
#pragma unroll
        for (int i = 0; i < 25; i++){
            float4 w = __ldg(a+i), u = xx[i];
            acc = fmaf(w.x,u.x,acc); acc = fmaf(w.y,u.y,acc);
            acc = fmaf(w.z,u.z,acc); acc = fmaf(w.w,u.w,acc);
        }
        sOg[tid] = acc;
    }
    __syncthreads();
    if (tid < 5){
        int q = tid;
        float bw0 = __ldg(&bW[0]);
        float qt = sQtw[q];
        float tmp[11]; float mx = -INFINITY;
#pragma unroll
        for (int s = 0; s < 11; s++){
            bool valid = (s == 0) || (t > RKN) || ((s-1) < t);
            float v = valid ? (qt + sKtw[s] + bw0) : NEGV;
            tmp[s] = v; mx = fmaxf(mx, v);
        }
        float se = 0.f, acc = 0.f;
#pragma unroll
        for (int s = 0; s < 11; s++){
            float e = expf(tmp[s] - mx);
            se += e; acc += e * sOg[q*11 + s];
        }
        sP[q] = acc / se;
    }
    __syncthreads();
    if (tid == 0){
        float p = sP[0] + sP[1] + sP[2] + sP[3] + sP[4];
        int col = (t == 0) ? 0 : (t + 1);
        out[b*SEQ + col] = p;
    }
}

// ---------------- launch ----------------
extern "C" void kernel_launch(void* const* d_in, const int* in_sizes, int n_in,
                              void* d_out, int out_size){
    const float* Eq     = (const float*)d_in[0];
    const float* Ec     = (const float*)d_in[1];
    const float* Er     = (const float*)d_in[2];
    const float* Wih1   = (const float*)d_in[3];
    const float* Whh1   = (const float*)d_in[4];
    const float* bih1   = (const float*)d_in[5];
    const float* bhh1   = (const float*)d_in[6];
    const float* Wih2   = (const float*)d_in[7];
    const float* Whh2   = (const float*)d_in[8];
    const float* bih2   = (const float*)d_in[9];
    const float* bhh2   = (const float*)d_in[10];
    const float* Wagg   = (const float*)d_in[11];
    const float* bagg   = (const float*)d_in[12];
    const float* Wlast  = (const float*)d_in[13];
    const float* blast  = (const float*)d_in[14];
    const float* Wquery = (const float*)d_in[15];
    const float* bquery = (const float*)d_in[16];
    const float* Wkey   = (const float*)d_in[17];
    const float* bkey   = (const float*)d_in[18];
    const float* WW     = (const float*)d_in[19];
    const float* bW     = (const float*)d_in[20];
    const float* h1i    = (const float*)d_in[21];
    const float* h2i    = (const float*)d_in[22];
    const int* question = (const int*)d_in[23];
    const int* response = (const int*)d_in[24];
    const int* maskp    = (const int*)d_in[25];
    const int* qnb      = (const int*)d_in[26];
    const int* snb      = (const int*)d_in[27];
    const int* cidx     = (const int*)d_in[28];
    const void* cmask   = d_in[29];
    float* out = (float*)d_out;

    cudaFuncSetAttribute(k_scan2, cudaFuncAttributeMaxDynamicSharedMemorySize, 122880);

    k_pre<<<2048, 256>>>(Eq, question, (const unsigned char*)cmask, bquery, WW,
                         Wih1, bih1, Er, out);
    k_gmat<<<dim3(4, BATCH), 256>>>();
    {
        int nwarp = 116*BATCH;
        int nb = (nwarp + 7) / 8;
        k_topk<<<nb, 256>>>();
    }
    k_aggqc<<<TSTEPS*BATCH, 256>>>(Eq, Ec, question, maskp, qnb, snb,
                                   Wagg, bagg, Wlast, blast,
                                   cidx, cmask, Wkey, bkey, WW);
    k_gi1<<<dim3(TSTEPS, 2), 256>>>(Wih1, response);
    k_scan2<<<128, 320, 120000>>>(Whh1, bhh1, Wih2, bih2, Whh2, bhh2, h1i, h2i);
    k_ktw<<<TSTEPS*BATCH/4, 128>>>(Wquery, bquery, WW);
    k_predict<<<TSTEPS*BATCH, 128>>>(bW, out);
}